// round 9
// baseline (speedup 1.0000x reference)
#include <cuda_runtime.h>
#include <cuda_fp16.h>
#include <cstdint>

#define NB 8
#define TDIM 4096
#define SDIM 512
#define CDIM 1024
#define NCHUNK 16
#define CHROWS (TDIM / NCHUNK)
#define NEG_INF (-3.0e38f)

typedef __half hf;

// ---------------- scratch (static device globals; no allocation) ----------------
__device__ float g_sc [(size_t)NB * TDIM * SDIM];
__device__ float g_vsc[(size_t)NB * SDIM * TDIM];
__device__ __align__(16) hf g_Xh [(size_t)NB * TDIM * CDIM], g_Xl [(size_t)NB * TDIM * CDIM];
__device__ __align__(16) hf g_XTh[(size_t)NB * CDIM * TDIM];
__device__ __align__(16) hf g_Kh [(size_t)NB * SDIM * CDIM];
__device__ __align__(16) hf g_Vh [(size_t)NB * SDIM * CDIM], g_Vl [(size_t)NB * SDIM * CDIM];
__device__ __align__(16) hf g_VTh[(size_t)NB * CDIM * SDIM];
__device__ __align__(16) hf g_Ph [(size_t)NB * TDIM * SDIM];
__device__ __align__(16) hf g_P2h[(size_t)NB * SDIM * TDIM];
__device__ __align__(16) hf g_P3h[(size_t)NB * SDIM * TDIM];
__device__ float g_pcm[NB * NCHUNK * SDIM], g_pcs[NB * NCHUNK * SDIM];
__device__ float g_cm [NB * SDIM], g_cs [NB * SDIM];

// ---------------- PTX helpers ----------------
__device__ __forceinline__ void cp16(uint32_t dst, const void* src) {
    asm volatile("cp.async.cg.shared.global [%0], [%1], 16;" :: "r"(dst), "l"(src));
}
__device__ __forceinline__ void cp_commit() {
    asm volatile("cp.async.commit_group;" ::: "memory");
}
template <int N>
__device__ __forceinline__ void cp_wait() {
    asm volatile("cp.async.wait_group %0;" :: "n"(N) : "memory");
}
__device__ __forceinline__ void ldsm4(uint32_t* r, uint32_t addr) {
    asm volatile("ldmatrix.sync.aligned.m8n8.x4.shared.b16 {%0,%1,%2,%3}, [%4];"
                 : "=r"(r[0]), "=r"(r[1]), "=r"(r[2]), "=r"(r[3]) : "r"(addr));
}
__device__ __forceinline__ void mma16816(float* d, const uint32_t* a, const uint32_t* b) {
    asm volatile(
        "mma.sync.aligned.m16n8k16.row.col.f32.f16.f16.f32 "
        "{%0,%1,%2,%3}, {%4,%5,%6,%7}, {%8,%9}, {%0,%1,%2,%3};"
        : "+f"(d[0]), "+f"(d[1]), "+f"(d[2]), "+f"(d[3])
        : "r"(a[0]), "r"(a[1]), "r"(a[2]), "r"(a[3]), "r"(b[0]), "r"(b[1]));
}
__device__ __forceinline__ void split1(float f, hf& h, hf& l) {
    h = __float2half_rn(f);
    l = __float2half_rn(f - __half2float(h));
}

// ---------------------------------------------------------------------------
// fp16 emulated GEMM on HMMA. Tile 128x128, BK=32, 256 thr, warp tile 64x32;
// 3-stage cp.async, 2 CTAs/SM.
// PASSES=2: D = Ah*Bh + Al*Bh.   PASSES=1: D = Ah*Bh (A-lo never loaded).
// ---------------------------------------------------------------------------
#define STAGE 32768
#define BOFF  16384

template <int PASSES, bool ADD>
__global__ void __launch_bounds__(256, 2)
mma_gemm(const hf* __restrict__ Ah, const hf* __restrict__ Al,
         const hf* __restrict__ Bh,
         const float* __restrict__ Res, float* __restrict__ C,
         float scale, int K, int Nglob, size_t sA, size_t sB, size_t sC)
{
    extern __shared__ char dsm[];
    const uint32_t sbase = (uint32_t)__cvta_generic_to_shared(dsm);
    const int tid = threadIdx.x, wid = tid >> 5, lane = tid & 31;
    const int b = blockIdx.z, m0 = blockIdx.y * 128, n0 = blockIdx.x * 128;
    const int wm = wid & 1, wn = wid >> 1;

    const hf* pAh = Ah + (size_t)b * sA;
    const hf* pAl = (PASSES == 2) ? (Al + (size_t)b * sA) : nullptr;
    const hf* pBh = Bh + (size_t)b * sB;

    const int KT = K >> 5;

    auto load = [&](int kc, int s) {
        uint32_t st = sbase + s * STAGE;
#pragma unroll
        for (int t = 0; t < 8; t++) {
            int idx = t * 256 + tid;
            int reg = idx >> 10;               // 0 = A, 1 = B
            int ch  = idx & 1023;
            int row = ch >> 3, c = ch & 7;
            int plane = c >> 2, cc = c & 3;    // hi chunks 0-3, lo chunks 4-7
            if (plane == 1 && (reg == 1 || PASSES == 1)) continue;  // no B-lo; no A-lo if 1-pass
            const hf* src = reg ? pBh : (plane ? pAl : pAh);
            int rbase = reg ? n0 : m0;
            uint32_t dst = st + (uint32_t)(reg * BOFF + row * 128 + ((c ^ (row & 7)) * 16));
            cp16(dst, (const char*)src + ((size_t)(rbase + row) * K + kc * 32 + cc * 8) * 2);
        }
        cp_commit();
    };

    float acc[4][4][4];
#pragma unroll
    for (int mi = 0; mi < 4; mi++)
#pragma unroll
        for (int ni = 0; ni < 4; ni++)
#pragma unroll
            for (int j = 0; j < 4; j++) acc[mi][ni][j] = 0.f;

    const int rowa = wm * 64 + (lane & 15);
    const int ka   = lane >> 4;
    const int xa   = rowa & 7;
    const int rowb = wn * 32 + (lane & 7) + ((lane >> 4) << 3);
    const int kb   = (lane >> 3) & 1;
    const int xb   = rowb & 7;

    auto compute = [&](int s) {
        uint32_t st = sbase + s * STAGE;
#pragma unroll
        for (int ks = 0; ks < 2; ks++) {
            uint32_t ah[4][4], al[4][4], bh[2][4];
#pragma unroll
            for (int mi = 0; mi < 4; mi++) {
                uint32_t rb = st + (uint32_t)((rowa + mi * 16) * 128);
                ldsm4(ah[mi], rb + (uint32_t)(((2 * ks + ka) ^ xa) * 16));
                if (PASSES == 2)
                    ldsm4(al[mi], rb + (uint32_t)(((4 + 2 * ks + ka) ^ xa) * 16));
            }
#pragma unroll
            for (int j = 0; j < 2; j++) {
                uint32_t rb = st + BOFF + (uint32_t)((rowb + j * 16) * 128);
                ldsm4(bh[j], rb + (uint32_t)(((2 * ks + kb) ^ xb) * 16));
            }
#pragma unroll
            for (int mi = 0; mi < 4; mi++)
#pragma unroll
                for (int j = 0; j < 2; j++) {
                    mma16816(acc[mi][2 * j],     ah[mi], bh[j]);
                    mma16816(acc[mi][2 * j + 1], ah[mi], bh[j] + 2);
                }
            if (PASSES == 2) {
#pragma unroll
                for (int mi = 0; mi < 4; mi++)
#pragma unroll
                    for (int j = 0; j < 2; j++) {
                        mma16816(acc[mi][2 * j],     al[mi], bh[j]);
                        mma16816(acc[mi][2 * j + 1], al[mi], bh[j] + 2);
                    }
            }
        }
    };

    load(0, 0);
    if (KT > 1) load(1, 1);

    for (int ci = 0; ci < KT; ci++) {
        if (ci < KT - 1) cp_wait<1>(); else cp_wait<0>();
        __syncthreads();
        if (ci + 2 < KT) load(ci + 2, (ci + 2) % 3);
        compute(ci % 3);
    }

    float* Co = C + (size_t)b * sC;
    const float* Rp = ADD ? (Res + (size_t)b * sC) : nullptr;
    const int rbase = m0 + wm * 64 + (lane >> 2);
    const int cbase = n0 + wn * 32 + (lane & 3) * 2;
#pragma unroll
    for (int mi = 0; mi < 4; mi++) {
#pragma unroll
        for (int ni = 0; ni < 4; ni++) {
#pragma unroll
            for (int h = 0; h < 2; h++) {
                int r = rbase + mi * 16 + h * 8;
                int c = cbase + ni * 8;
                float2 v;
                v.x = acc[mi][ni][2 * h]     * scale;
                v.y = acc[mi][ni][2 * h + 1] * scale;
                size_t go = (size_t)r * Nglob + c;
                if (ADD) {
                    float2 d = *(const float2*)(Rp + go);
                    v.x += d.x; v.y += d.y;
                }
                *(float2*)(Co + go) = v;
            }
        }
    }
}

// ---------------- fused conversion kernels ----------------
// split (hi+lo) + transposed split (hi only) in one pass
__global__ void stx_k(const float* __restrict__ in, hf* __restrict__ oh,
                      hf* __restrict__ ol, hf* __restrict__ ohT, int R, int Cc)
{
    __shared__ float t[32][33];
    int b = blockIdx.z;
    int c0 = blockIdx.x * 32, r0 = blockIdx.y * 32;
    const float* ip = in + (size_t)b * R * Cc;
    size_t nb = (size_t)b * R * Cc;
    int tx = threadIdx.x, ty = threadIdx.y;
#pragma unroll
    for (int i = 0; i < 4; i++) {
        int r = r0 + ty + i * 8;
        float v = ip[(size_t)r * Cc + c0 + tx];
        t[ty + i * 8][tx] = v;
        hf h, l;
        split1(v, h, l);
        oh[nb + (size_t)r * Cc + c0 + tx] = h;
        if (ol) ol[nb + (size_t)r * Cc + c0 + tx] = l;
    }
    __syncthreads();
#pragma unroll
    for (int i = 0; i < 4; i++) {
        int c = c0 + ty + i * 8;
        ohT[nb + (size_t)c * R + r0 + tx] = __float2half_rn(t[tx][ty + i * 8]);
    }
}

// hi-only conversion (K)
__global__ void splith_k(const float* __restrict__ in, hf* __restrict__ h, size_t n4)
{
    size_t i = (size_t)blockIdx.x * blockDim.x + threadIdx.x;
    if (i >= n4) return;
    float4 v = ((const float4*)in)[i];
    __half2* hp = (__half2*)h;
    hp[i * 2]     = __halves2half2(__float2half_rn(v.x), __float2half_rn(v.y));
    hp[i * 2 + 1] = __halves2half2(__float2half_rn(v.z), __float2half_rn(v.w));
}

// row softmax over 512 -> fp16 hi only
__global__ void softrow512_k(const float* __restrict__ S, hf* __restrict__ oh)
{
    int warp = threadIdx.x >> 5, lane = threadIdx.x & 31;
    size_t row = (size_t)blockIdx.x * 8 + warp;
    const float4* p4 = (const float4*)(S + row * SDIM);
    float4 v[4];
    float m = NEG_INF;
#pragma unroll
    for (int i = 0; i < 4; i++) {
        v[i] = p4[lane + i * 32];
        m = fmaxf(m, fmaxf(fmaxf(v[i].x, v[i].y), fmaxf(v[i].z, v[i].w)));
    }
#pragma unroll
    for (int o = 16; o > 0; o >>= 1) m = fmaxf(m, __shfl_xor_sync(0xffffffffu, m, o));
    float s = 0.f;
#pragma unroll
    for (int i = 0; i < 4; i++)
        s += __expf(v[i].x - m) + __expf(v[i].y - m) + __expf(v[i].z - m) + __expf(v[i].w - m);
#pragma unroll
    for (int o = 16; o > 0; o >>= 1) s += __shfl_xor_sync(0xffffffffu, s, o);
    float inv = __fdividef(1.0f, s);
    __half2* hp = (__half2*)(oh + row * SDIM);
#pragma unroll
    for (int i = 0; i < 4; i++) {
        int p = (lane + i * 32) * 2;
        hp[p]     = __halves2half2(__float2half_rn(__expf(v[i].x - m) * inv),
                                   __float2half_rn(__expf(v[i].y - m) * inv));
        hp[p + 1] = __halves2half2(__float2half_rn(__expf(v[i].z - m) * inv),
                                   __float2half_rn(__expf(v[i].w - m) * inv));
    }
}

// row softmax over 4096 -> fp16 hi only
__global__ void softrow4096_k(const float* __restrict__ S, hf* __restrict__ oh)
{
    __shared__ float sh[16];
    int tid = threadIdx.x, lane = tid & 31, warp = tid >> 5;
    size_t row = blockIdx.x;
    const float4* p4 = (const float4*)(S + row * TDIM);
    float4 v[2];
    float m = NEG_INF;
#pragma unroll
    for (int i = 0; i < 2; i++) {
        v[i] = p4[tid + i * 512];
        m = fmaxf(m, fmaxf(fmaxf(v[i].x, v[i].y), fmaxf(v[i].z, v[i].w)));
    }
#pragma unroll
    for (int o = 16; o > 0; o >>= 1) m = fmaxf(m, __shfl_xor_sync(0xffffffffu, m, o));
    if (!lane) sh[warp] = m;
    __syncthreads();
    if (tid < 16) {
        float t = sh[tid];
#pragma unroll
        for (int o = 8; o > 0; o >>= 1) t = fmaxf(t, __shfl_xor_sync(0xffffu, t, o));
        if (!tid) sh[0] = t;
    }
    __syncthreads();
    m = sh[0];
    __syncthreads();
    float s = 0.f;
#pragma unroll
    for (int i = 0; i < 2; i++)
        s += __expf(v[i].x - m) + __expf(v[i].y - m) + __expf(v[i].z - m) + __expf(v[i].w - m);
#pragma unroll
    for (int o = 16; o > 0; o >>= 1) s += __shfl_xor_sync(0xffffffffu, s, o);
    if (!lane) sh[warp] = s;
    __syncthreads();
    if (tid < 16) {
        float t = sh[tid];
#pragma unroll
        for (int o = 8; o > 0; o >>= 1) t += __shfl_xor_sync(0xffffu, t, o);
        if (!tid) sh[0] = t;
    }
    __syncthreads();
    float inv = __fdividef(1.0f, sh[0]);
    __half2* hp = (__half2*)(oh + row * TDIM);
#pragma unroll
    for (int i = 0; i < 2; i++) {
        int p = (tid + i * 512) * 2;
        hp[p]     = __halves2half2(__float2half_rn(__expf(v[i].x - m) * inv),
                                   __float2half_rn(__expf(v[i].y - m) * inv));
        hp[p + 1] = __halves2half2(__float2half_rn(__expf(v[i].z - m) * inv),
                                   __float2half_rn(__expf(v[i].w - m) * inv));
    }
}

// ---------------- column softmax (over T) pipeline ----------------
__global__ void colpart_k(const float* __restrict__ S, float* __restrict__ pm,
                          float* __restrict__ ps)
{
    int b = blockIdx.y, ch = blockIdx.x, s = threadIdx.x;
    const float* p = S + (size_t)b * TDIM * SDIM + (size_t)ch * CHROWS * SDIM + s;
    float m = NEG_INF, sum = 0.f;
    for (int t = 0; t < CHROWS; t++) {
        float v = p[(size_t)t * SDIM];
        float nm = fmaxf(m, v);
        sum = sum * __expf(m - nm) + __expf(v - nm);
        m = nm;
    }
    int o = (b * NCHUNK + ch) * SDIM + s;
    pm[o] = m; ps[o] = sum;
}

__global__ void colcomb_k(const float* __restrict__ pm, const float* __restrict__ ps,
                          float* __restrict__ cm, float* __restrict__ cs)
{
    int b = blockIdx.x, s = threadIdx.x;
    float m = NEG_INF;
#pragma unroll
    for (int c = 0; c < NCHUNK; c++) m = fmaxf(m, pm[(b * NCHUNK + c) * SDIM + s]);
    float sum = 0.f;
#pragma unroll
    for (int c = 0; c < NCHUNK; c++)
        sum += ps[(b * NCHUNK + c) * SDIM + s] * __expf(pm[(b * NCHUNK + c) * SDIM + s] - m);
    cm[b * SDIM + s] = m;
    cs[b * SDIM + s] = sum;
}

// col softmax + transpose -> [S,T] fp16 hi only
__global__ void pcolT_k(const float* __restrict__ sc, const float* __restrict__ cm,
                        const float* __restrict__ cs, hf* __restrict__ oh)
{
    __shared__ float t[32][33];
    int b = blockIdx.z;
    int s0 = blockIdx.x * 32, t0 = blockIdx.y * 32;
    const float* ip = sc + (size_t)b * TDIM * SDIM;
    int tx = threadIdx.x, ty = threadIdx.y;
#pragma unroll
    for (int i = 0; i < 4; i++)
        t[ty + i * 8][tx] = ip[(size_t)(t0 + ty + i * 8) * SDIM + s0 + tx];
    __syncthreads();
    size_t ob = (size_t)b * SDIM * TDIM;
#pragma unroll
    for (int i = 0; i < 4; i++) {
        int s = s0 + ty + i * 8;
        float m = cm[b * SDIM + s], inv = __fdividef(1.0f, cs[b * SDIM + s]);
        oh[ob + (size_t)s * TDIM + t0 + tx] =
            __float2half_rn(__expf(t[tx][ty + i * 8] - m) * inv);
    }
}

// ---------------- launch ----------------
extern "C" void kernel_launch(void* const* d_in, const int* in_sizes, int n_in,
                              void* d_out, int out_size)
{
    const float* x   = (const float*)d_in[0];
    const float* kin = (const float*)d_in[1];
    const float* vin = (const float*)d_in[2];

    float* att = (float*)d_out;
    float* ktv = att + (size_t)NB * TDIM * CDIM;
    float* vtv = ktv + (size_t)NB * SDIM * CDIM;

    float *sc, *vsc, *pcm, *pcs, *cm, *cs;
    hf *Xh, *Xl, *XTh, *Kh, *Vh, *Vl, *VTh;
    hf *Ph, *P2h, *P3h;
    cudaGetSymbolAddress((void**)&sc, g_sc);     cudaGetSymbolAddress((void**)&vsc, g_vsc);
    cudaGetSymbolAddress((void**)&pcm, g_pcm);   cudaGetSymbolAddress((void**)&pcs, g_pcs);
    cudaGetSymbolAddress((void**)&cm, g_cm);     cudaGetSymbolAddress((void**)&cs, g_cs);
    cudaGetSymbolAddress((void**)&Xh, g_Xh);     cudaGetSymbolAddress((void**)&Xl, g_Xl);
    cudaGetSymbolAddress((void**)&XTh, g_XTh);
    cudaGetSymbolAddress((void**)&Kh, g_Kh);
    cudaGetSymbolAddress((void**)&Vh, g_Vh);     cudaGetSymbolAddress((void**)&Vl, g_Vl);
    cudaGetSymbolAddress((void**)&VTh, g_VTh);
    cudaGetSymbolAddress((void**)&Ph, g_Ph);
    cudaGetSymbolAddress((void**)&P2h, g_P2h);
    cudaGetSymbolAddress((void**)&P3h, g_P3h);

    const int SMEM = 3 * STAGE;  // 98304
    cudaFuncSetAttribute(mma_gemm<2, false>, cudaFuncAttributeMaxDynamicSharedMemorySize, SMEM);
    cudaFuncSetAttribute(mma_gemm<1, false>, cudaFuncAttributeMaxDynamicSharedMemorySize, SMEM);
    cudaFuncSetAttribute(mma_gemm<1, true>,  cudaFuncAttributeMaxDynamicSharedMemorySize, SMEM);

    const float scale = 0.03125f;  // 1/sqrt(1024)

    // operand prep
    stx_k<<<dim3(CDIM / 32, TDIM / 32, NB), dim3(32, 8)>>>(x, Xh, Xl, XTh, TDIM, CDIM);
    {
        size_t n4 = (size_t)NB * SDIM * CDIM / 4;
        splith_k<<<(unsigned)((n4 + 255) / 256), 256>>>(kin, Kh, n4);
    }
    stx_k<<<dim3(CDIM / 32, SDIM / 32, NB), dim3(32, 8)>>>(vin, Vh, Vl, VTh, SDIM, CDIM);

    // 1) scores = scale * X K^T  [T,S]  (2-pass; must stay accurate pre-softmax)
    mma_gemm<2, false><<<dim3(SDIM / 128, TDIM / 128, NB), 256, SMEM>>>(
        Xh, Xl, Kh, nullptr, sc, scale, CDIM, SDIM,
        (size_t)TDIM * CDIM, (size_t)SDIM * CDIM, (size_t)TDIM * SDIM);

    // softmax conversions
    softrow512_k<<<NB * TDIM / 8, 256>>>(sc, Ph);
    colpart_k<<<dim3(NCHUNK, NB), 512>>>(sc, pcm, pcs);
    colcomb_k<<<NB, 512>>>(pcm, pcs, cm, cs);
    pcolT_k<<<dim3(SDIM / 32, TDIM / 32, NB), dim3(32, 8)>>>(sc, cm, cs, P2h);

    // 2) att = P V   (1-pass; weight-relative error 2^-12 acceptable, K=512)
    mma_gemm<1, false><<<dim3(CDIM / 128, TDIM / 128, NB), 256, SMEM>>>(
        Ph, nullptr, VTh, nullptr, att, 1.0f, SDIM, CDIM,
        (size_t)TDIM * SDIM, (size_t)CDIM * SDIM, (size_t)TDIM * CDIM);

    // 3) k_t = k + P2^T X   (1-pass; residual-dominated, K=4096)
    mma_gemm<1, true><<<dim3(CDIM / 128, SDIM / 128, NB), 256, SMEM>>>(
        P2h, nullptr, XTh, kin, ktv, 1.0f, TDIM, CDIM,
        (size_t)SDIM * TDIM, (size_t)CDIM * TDIM, (size_t)SDIM * CDIM);

    // 4) v_scores = scale * V X^T  [S,T]  (2-pass; must stay accurate pre-softmax)
    mma_gemm<2, false><<<dim3(TDIM / 128, SDIM / 128, NB), 256, SMEM>>>(
        Vh, Vl, Xh, nullptr, vsc, scale, CDIM, TDIM,
        (size_t)SDIM * CDIM, (size_t)TDIM * CDIM, (size_t)SDIM * TDIM);

    // P3 (row softmax over 4096, hi only)
    softrow4096_k<<<NB * SDIM, 512>>>(vsc, P3h);

    // 5) v_t = v + P3 X   (1-pass; residual-dominated, K=4096)
    mma_gemm<1, true><<<dim3(CDIM / 128, SDIM / 128, NB), 256, SMEM>>>(
        P3h, nullptr, XTh, vin, vtv, 1.0f, TDIM, CDIM,
        (size_t)SDIM * TDIM, (size_t)CDIM * TDIM, (size_t)SDIM * CDIM);
}

// round 10
// speedup vs baseline: 1.5074x; 1.5074x over previous
#include <cuda_runtime.h>
#include <cuda_fp16.h>
#include <cstdint>

#define NB 8
#define TDIM 4096
#define SDIM 512
#define CDIM 1024
#define NCHUNK 16
#define CHROWS (TDIM / NCHUNK)
#define NEG_INF (-3.0e38f)

typedef __half hf;

// ---------------- scratch (static device globals; no allocation) ----------------
__device__ float g_sc [(size_t)NB * TDIM * SDIM];
__device__ float g_vsc[(size_t)NB * SDIM * TDIM];
__device__ __align__(16) hf g_Xh [(size_t)NB * TDIM * CDIM], g_Xl [(size_t)NB * TDIM * CDIM];
__device__ __align__(16) hf g_XTh[(size_t)NB * CDIM * TDIM];
__device__ __align__(16) hf g_Kh [(size_t)NB * SDIM * CDIM];
__device__ __align__(16) hf g_Vh [(size_t)NB * SDIM * CDIM], g_Vl [(size_t)NB * SDIM * CDIM];
__device__ __align__(16) hf g_VTh[(size_t)NB * CDIM * SDIM];
__device__ __align__(16) hf g_Ph [(size_t)NB * TDIM * SDIM];
__device__ __align__(16) hf g_P2h[(size_t)NB * SDIM * TDIM];
__device__ __align__(16) hf g_P3h[(size_t)NB * SDIM * TDIM];
__device__ float g_pcm[NB * NCHUNK * SDIM], g_pcs[NB * NCHUNK * SDIM];
__device__ float g_cm [NB * SDIM], g_cs [NB * SDIM];

// ---------------- PTX helpers ----------------
__device__ __forceinline__ void cp16(uint32_t dst, const void* src) {
    asm volatile("cp.async.cg.shared.global [%0], [%1], 16;" :: "r"(dst), "l"(src));
}
__device__ __forceinline__ void cp_commit() {
    asm volatile("cp.async.commit_group;" ::: "memory");
}
template <int N>
__device__ __forceinline__ void cp_wait() {
    asm volatile("cp.async.wait_group %0;" :: "n"(N) : "memory");
}
__device__ __forceinline__ void ldsm4(uint32_t* r, uint32_t addr) {
    asm volatile("ldmatrix.sync.aligned.m8n8.x4.shared.b16 {%0,%1,%2,%3}, [%4];"
                 : "=r"(r[0]), "=r"(r[1]), "=r"(r[2]), "=r"(r[3]) : "r"(addr));
}
__device__ __forceinline__ void mma16816(float* d, const uint32_t* a, const uint32_t* b) {
    asm volatile(
        "mma.sync.aligned.m16n8k16.row.col.f32.f16.f16.f32 "
        "{%0,%1,%2,%3}, {%4,%5,%6,%7}, {%8,%9}, {%0,%1,%2,%3};"
        : "+f"(d[0]), "+f"(d[1]), "+f"(d[2]), "+f"(d[3])
        : "r"(a[0]), "r"(a[1]), "r"(a[2]), "r"(a[3]), "r"(b[0]), "r"(b[1]));
}
__device__ __forceinline__ void split1(float f, hf& h, hf& l) {
    h = __float2half_rn(f);
    l = __float2half_rn(f - __half2float(h));
}

// ---------------------------------------------------------------------------
// fp16 emulated GEMM on HMMA. Tile 128x128, BK=32, 256 thr, warp tile 64x32;
// 3-stage cp.async, 2 CTAs/SM.
// PASSES=2: D = Ah*Bh + Al*Bh.   PASSES=1: D = Ah*Bh (A-lo never loaded).
// ---------------------------------------------------------------------------
#define STAGE 32768
#define BOFF  16384

template <int PASSES, bool ADD>
__global__ void __launch_bounds__(256, 2)
mma_gemm(const hf* __restrict__ Ah, const hf* __restrict__ Al,
         const hf* __restrict__ Bh,
         const float* __restrict__ Res, float* __restrict__ C,
         float scale, int K, int Nglob, size_t sA, size_t sB, size_t sC)
{
    extern __shared__ char dsm[];
    const uint32_t sbase = (uint32_t)__cvta_generic_to_shared(dsm);
    const int tid = threadIdx.x, wid = tid >> 5, lane = tid & 31;
    const int b = blockIdx.z, m0 = blockIdx.y * 128, n0 = blockIdx.x * 128;
    const int wm = wid & 1, wn = wid >> 1;

    const hf* pAh = Ah + (size_t)b * sA;
    const hf* pAl = (PASSES == 2) ? (Al + (size_t)b * sA) : nullptr;
    const hf* pBh = Bh + (size_t)b * sB;

    const int KT = K >> 5;

    auto load = [&](int kc, int s) {
        uint32_t st = sbase + s * STAGE;
#pragma unroll
        for (int t = 0; t < 8; t++) {
            int idx = t * 256 + tid;
            int reg = idx >> 10;               // 0 = A, 1 = B
            int ch  = idx & 1023;
            int row = ch >> 3, c = ch & 7;
            int plane = c >> 2, cc = c & 3;    // hi chunks 0-3, lo chunks 4-7
            if (plane == 1 && (reg == 1 || PASSES == 1)) continue;  // no B-lo; no A-lo if 1-pass
            const hf* src = reg ? pBh : (plane ? pAl : pAh);
            int rbase = reg ? n0 : m0;
            uint32_t dst = st + (uint32_t)(reg * BOFF + row * 128 + ((c ^ (row & 7)) * 16));
            cp16(dst, (const char*)src + ((size_t)(rbase + row) * K + kc * 32 + cc * 8) * 2);
        }
        cp_commit();
    };

    float acc[4][4][4];
#pragma unroll
    for (int mi = 0; mi < 4; mi++)
#pragma unroll
        for (int ni = 0; ni < 4; ni++)
#pragma unroll
            for (int j = 0; j < 4; j++) acc[mi][ni][j] = 0.f;

    const int rowa = wm * 64 + (lane & 15);
    const int ka   = lane >> 4;
    const int xa   = rowa & 7;
    const int rowb = wn * 32 + (lane & 7) + ((lane >> 4) << 3);
    const int kb   = (lane >> 3) & 1;
    const int xb   = rowb & 7;

    auto compute = [&](int s) {
        uint32_t st = sbase + s * STAGE;
#pragma unroll
        for (int ks = 0; ks < 2; ks++) {
            uint32_t ah[4][4], al[4][4], bh[2][4];
#pragma unroll
            for (int mi = 0; mi < 4; mi++) {
                uint32_t rb = st + (uint32_t)((rowa + mi * 16) * 128);
                ldsm4(ah[mi], rb + (uint32_t)(((2 * ks + ka) ^ xa) * 16));
                if (PASSES == 2)
                    ldsm4(al[mi], rb + (uint32_t)(((4 + 2 * ks + ka) ^ xa) * 16));
            }
#pragma unroll
            for (int j = 0; j < 2; j++) {
                uint32_t rb = st + BOFF + (uint32_t)((rowb + j * 16) * 128);
                ldsm4(bh[j], rb + (uint32_t)(((2 * ks + kb) ^ xb) * 16));
            }
#pragma unroll
            for (int mi = 0; mi < 4; mi++)
#pragma unroll
                for (int j = 0; j < 2; j++) {
                    mma16816(acc[mi][2 * j],     ah[mi], bh[j]);
                    mma16816(acc[mi][2 * j + 1], ah[mi], bh[j] + 2);
                }
            if (PASSES == 2) {
#pragma unroll
                for (int mi = 0; mi < 4; mi++)
#pragma unroll
                    for (int j = 0; j < 2; j++) {
                        mma16816(acc[mi][2 * j],     al[mi], bh[j]);
                        mma16816(acc[mi][2 * j + 1], al[mi], bh[j] + 2);
                    }
            }
        }
    };

    load(0, 0);
    if (KT > 1) load(1, 1);

    for (int ci = 0; ci < KT; ci++) {
        if (ci < KT - 1) cp_wait<1>(); else cp_wait<0>();
        __syncthreads();
        if (ci + 2 < KT) load(ci + 2, (ci + 2) % 3);
        compute(ci % 3);
    }

    float* Co = C + (size_t)b * sC;
    const float* Rp = ADD ? (Res + (size_t)b * sC) : nullptr;
    const int rbase = m0 + wm * 64 + (lane >> 2);
    const int cbase = n0 + wn * 32 + (lane & 3) * 2;
#pragma unroll
    for (int mi = 0; mi < 4; mi++) {
#pragma unroll
        for (int ni = 0; ni < 4; ni++) {
#pragma unroll
            for (int h = 0; h < 2; h++) {
                int r = rbase + mi * 16 + h * 8;
                int c = cbase + ni * 8;
                float2 v;
                v.x = acc[mi][ni][2 * h]     * scale;
                v.y = acc[mi][ni][2 * h + 1] * scale;
                size_t go = (size_t)r * Nglob + c;
                if (ADD) {
                    float2 d = *(const float2*)(Rp + go);
                    v.x += d.x; v.y += d.y;
                }
                *(float2*)(Co + go) = v;
            }
        }
    }
}

// ---------------- fused conversion kernels ----------------
// split (hi+lo) + transposed split (hi only) in one pass
__global__ void stx_k(const float* __restrict__ in, hf* __restrict__ oh,
                      hf* __restrict__ ol, hf* __restrict__ ohT, int R, int Cc)
{
    __shared__ float t[32][33];
    int b = blockIdx.z;
    int c0 = blockIdx.x * 32, r0 = blockIdx.y * 32;
    const float* ip = in + (size_t)b * R * Cc;
    size_t nb = (size_t)b * R * Cc;
    int tx = threadIdx.x, ty = threadIdx.y;
#pragma unroll
    for (int i = 0; i < 4; i++) {
        int r = r0 + ty + i * 8;
        float v = ip[(size_t)r * Cc + c0 + tx];
        t[ty + i * 8][tx] = v;
        hf h, l;
        split1(v, h, l);
        oh[nb + (size_t)r * Cc + c0 + tx] = h;
        if (ol) ol[nb + (size_t)r * Cc + c0 + tx] = l;
    }
    __syncthreads();
#pragma unroll
    for (int i = 0; i < 4; i++) {
        int c = c0 + ty + i * 8;
        ohT[nb + (size_t)c * R + r0 + tx] = __float2half_rn(t[tx][ty + i * 8]);
    }
}

// hi-only conversion (K)
__global__ void splith_k(const float* __restrict__ in, hf* __restrict__ h, size_t n4)
{
    size_t i = (size_t)blockIdx.x * blockDim.x + threadIdx.x;
    if (i >= n4) return;
    float4 v = ((const float4*)in)[i];
    __half2* hp = (__half2*)h;
    hp[i * 2]     = __halves2half2(__float2half_rn(v.x), __float2half_rn(v.y));
    hp[i * 2 + 1] = __halves2half2(__float2half_rn(v.z), __float2half_rn(v.w));
}

// row softmax over 512 -> fp16 hi only
__global__ void softrow512_k(const float* __restrict__ S, hf* __restrict__ oh)
{
    int warp = threadIdx.x >> 5, lane = threadIdx.x & 31;
    size_t row = (size_t)blockIdx.x * 8 + warp;
    const float4* p4 = (const float4*)(S + row * SDIM);
    float4 v[4];
    float m = NEG_INF;
#pragma unroll
    for (int i = 0; i < 4; i++) {
        v[i] = p4[lane + i * 32];
        m = fmaxf(m, fmaxf(fmaxf(v[i].x, v[i].y), fmaxf(v[i].z, v[i].w)));
    }
#pragma unroll
    for (int o = 16; o > 0; o >>= 1) m = fmaxf(m, __shfl_xor_sync(0xffffffffu, m, o));
    float s = 0.f;
#pragma unroll
    for (int i = 0; i < 4; i++)
        s += __expf(v[i].x - m) + __expf(v[i].y - m) + __expf(v[i].z - m) + __expf(v[i].w - m);
#pragma unroll
    for (int o = 16; o > 0; o >>= 1) s += __shfl_xor_sync(0xffffffffu, s, o);
    float inv = __fdividef(1.0f, s);
    __half2* hp = (__half2*)(oh + row * SDIM);
#pragma unroll
    for (int i = 0; i < 4; i++) {
        int p = (lane + i * 32) * 2;
        hp[p]     = __halves2half2(__float2half_rn(__expf(v[i].x - m) * inv),
                                   __float2half_rn(__expf(v[i].y - m) * inv));
        hp[p + 1] = __halves2half2(__float2half_rn(__expf(v[i].z - m) * inv),
                                   __float2half_rn(__expf(v[i].w - m) * inv));
    }
}

// row softmax over 4096 -> fp16 hi only
__global__ void softrow4096_k(const float* __restrict__ S, hf* __restrict__ oh)
{
    __shared__ float sh[16];
    int tid = threadIdx.x, lane = tid & 31, warp = tid >> 5;
    size_t row = blockIdx.x;
    const float4* p4 = (const float4*)(S + row * TDIM);
    float4 v[2];
    float m = NEG_INF;
#pragma unroll
    for (int i = 0; i < 2; i++) {
        v[i] = p4[tid + i * 512];
        m = fmaxf(m, fmaxf(fmaxf(v[i].x, v[i].y), fmaxf(v[i].z, v[i].w)));
    }
#pragma unroll
    for (int o = 16; o > 0; o >>= 1) m = fmaxf(m, __shfl_xor_sync(0xffffffffu, m, o));
    if (!lane) sh[warp] = m;
    __syncthreads();
    if (tid < 16) {
        float t = sh[tid];
#pragma unroll
        for (int o = 8; o > 0; o >>= 1) t = fmaxf(t, __shfl_xor_sync(0xffffu, t, o));
        if (!tid) sh[0] = t;
    }
    __syncthreads();
    m = sh[0];
    __syncthreads();
    float s = 0.f;
#pragma unroll
    for (int i = 0; i < 2; i++)
        s += __expf(v[i].x - m) + __expf(v[i].y - m) + __expf(v[i].z - m) + __expf(v[i].w - m);
#pragma unroll
    for (int o = 16; o > 0; o >>= 1) s += __shfl_xor_sync(0xffffffffu, s, o);
    if (!lane) sh[warp] = s;
    __syncthreads();
    if (tid < 16) {
        float t = sh[tid];
#pragma unroll
        for (int o = 8; o > 0; o >>= 1) t += __shfl_xor_sync(0xffffu, t, o);
        if (!tid) sh[0] = t;
    }
    __syncthreads();
    float inv = __fdividef(1.0f, sh[0]);
    __half2* hp = (__half2*)(oh + row * TDIM);
#pragma unroll
    for (int i = 0; i < 2; i++) {
        int p = (tid + i * 512) * 2;
        hp[p]     = __halves2half2(__float2half_rn(__expf(v[i].x - m) * inv),
                                   __float2half_rn(__expf(v[i].y - m) * inv));
        hp[p + 1] = __halves2half2(__float2half_rn(__expf(v[i].z - m) * inv),
                                   __float2half_rn(__expf(v[i].w - m) * inv));
    }
}

// ---------------- column softmax (over T) pipeline ----------------
__global__ void colpart_k(const float* __restrict__ S, float* __restrict__ pm,
                          float* __restrict__ ps)
{
    int b = blockIdx.y, ch = blockIdx.x, s = threadIdx.x;
    const float* p = S + (size_t)b * TDIM * SDIM + (size_t)ch * CHROWS * SDIM + s;
    float m = NEG_INF, sum = 0.f;
    for (int t = 0; t < CHROWS; t++) {
        float v = p[(size_t)t * SDIM];
        float nm = fmaxf(m, v);
        sum = sum * __expf(m - nm) + __expf(v - nm);
        m = nm;
    }
    int o = (b * NCHUNK + ch) * SDIM + s;
    pm[o] = m; ps[o] = sum;
}

__global__ void colcomb_k(const float* __restrict__ pm, const float* __restrict__ ps,
                          float* __restrict__ cm, float* __restrict__ cs)
{
    int b = blockIdx.x, s = threadIdx.x;
    float m = NEG_INF;
#pragma unroll
    for (int c = 0; c < NCHUNK; c++) m = fmaxf(m, pm[(b * NCHUNK + c) * SDIM + s]);
    float sum = 0.f;
#pragma unroll
    for (int c = 0; c < NCHUNK; c++)
        sum += ps[(b * NCHUNK + c) * SDIM + s] * __expf(pm[(b * NCHUNK + c) * SDIM + s] - m);
    cm[b * SDIM + s] = m;
    cs[b * SDIM + s] = sum;
}

// col softmax + transpose -> [S,T] fp16 hi only
__global__ void pcolT_k(const float* __restrict__ sc, const float* __restrict__ cm,
                        const float* __restrict__ cs, hf* __restrict__ oh)
{
    __shared__ float t[32][33];
    int b = blockIdx.z;
    int s0 = blockIdx.x * 32, t0 = blockIdx.y * 32;
    const float* ip = sc + (size_t)b * TDIM * SDIM;
    int tx = threadIdx.x, ty = threadIdx.y;
#pragma unroll
    for (int i = 0; i < 4; i++)
        t[ty + i * 8][tx] = ip[(size_t)(t0 + ty + i * 8) * SDIM + s0 + tx];
    __syncthreads();
    size_t ob = (size_t)b * SDIM * TDIM;
#pragma unroll
    for (int i = 0; i < 4; i++) {
        int s = s0 + ty + i * 8;
        float m = cm[b * SDIM + s], inv = __fdividef(1.0f, cs[b * SDIM + s]);
        oh[ob + (size_t)s * TDIM + t0 + tx] =
            __float2half_rn(__expf(t[tx][ty + i * 8] - m) * inv);
    }
}

// ---------------- launch ----------------
extern "C" void kernel_launch(void* const* d_in, const int* in_sizes, int n_in,
                              void* d_out, int out_size)
{
    const float* x   = (const float*)d_in[0];
    const float* kin = (const float*)d_in[1];
    const float* vin = (const float*)d_in[2];

    float* att = (float*)d_out;
    float* ktv = att + (size_t)NB * TDIM * CDIM;
    float* vtv = ktv + (size_t)NB * SDIM * CDIM;

    float *sc, *vsc, *pcm, *pcs, *cm, *cs;
    hf *Xh, *Xl, *XTh, *Kh, *Vh, *Vl, *VTh;
    hf *Ph, *P2h, *P3h;
    cudaGetSymbolAddress((void**)&sc, g_sc);     cudaGetSymbolAddress((void**)&vsc, g_vsc);
    cudaGetSymbolAddress((void**)&pcm, g_pcm);   cudaGetSymbolAddress((void**)&pcs, g_pcs);
    cudaGetSymbolAddress((void**)&cm, g_cm);     cudaGetSymbolAddress((void**)&cs, g_cs);
    cudaGetSymbolAddress((void**)&Xh, g_Xh);     cudaGetSymbolAddress((void**)&Xl, g_Xl);
    cudaGetSymbolAddress((void**)&XTh, g_XTh);
    cudaGetSymbolAddress((void**)&Kh, g_Kh);
    cudaGetSymbolAddress((void**)&Vh, g_Vh);     cudaGetSymbolAddress((void**)&Vl, g_Vl);
    cudaGetSymbolAddress((void**)&VTh, g_VTh);
    cudaGetSymbolAddress((void**)&Ph, g_Ph);
    cudaGetSymbolAddress((void**)&P2h, g_P2h);
    cudaGetSymbolAddress((void**)&P3h, g_P3h);

    const int SMEM = 3 * STAGE;  // 98304
    cudaFuncSetAttribute(mma_gemm<2, false>, cudaFuncAttributeMaxDynamicSharedMemorySize, SMEM);
    cudaFuncSetAttribute(mma_gemm<1, false>, cudaFuncAttributeMaxDynamicSharedMemorySize, SMEM);
    cudaFuncSetAttribute(mma_gemm<1, true>,  cudaFuncAttributeMaxDynamicSharedMemorySize, SMEM);

    const float scale = 0.03125f;  // 1/sqrt(1024)

    // operand prep
    stx_k<<<dim3(CDIM / 32, TDIM / 32, NB), dim3(32, 8)>>>(x, Xh, Xl, XTh, TDIM, CDIM);
    {
        size_t n4 = (size_t)NB * SDIM * CDIM / 4;
        splith_k<<<(unsigned)((n4 + 255) / 256), 256>>>(kin, Kh, n4);
    }
    stx_k<<<dim3(CDIM / 32, SDIM / 32, NB), dim3(32, 8)>>>(vin, Vh, Vl, VTh, SDIM, CDIM);

    // 1) scores = scale * X K^T  [T,S]  (2-pass; must stay accurate pre-softmax)
    mma_gemm<2, false><<<dim3(SDIM / 128, TDIM / 128, NB), 256, SMEM>>>(
        Xh, Xl, Kh, nullptr, sc, scale, CDIM, SDIM,
        (size_t)TDIM * CDIM, (size_t)SDIM * CDIM, (size_t)TDIM * SDIM);

    // softmax conversions
    softrow512_k<<<NB * TDIM / 8, 256>>>(sc, Ph);
    colpart_k<<<dim3(NCHUNK, NB), 512>>>(sc, pcm, pcs);
    colcomb_k<<<NB, 512>>>(pcm, pcs, cm, cs);
    pcolT_k<<<dim3(SDIM / 32, TDIM / 32, NB), dim3(32, 8)>>>(sc, cm, cs, P2h);

    // 2) att = P V   (1-pass; weight-relative error 2^-12 acceptable, K=512)
    mma_gemm<1, false><<<dim3(CDIM / 128, TDIM / 128, NB), 256, SMEM>>>(
        Ph, nullptr, VTh, nullptr, att, 1.0f, SDIM, CDIM,
        (size_t)TDIM * SDIM, (size_t)CDIM * SDIM, (size_t)TDIM * CDIM);

    // 3) k_t = k + P2^T X   (1-pass; residual-dominated, K=4096)
    mma_gemm<1, true><<<dim3(CDIM / 128, SDIM / 128, NB), 256, SMEM>>>(
        P2h, nullptr, XTh, kin, ktv, 1.0f, TDIM, CDIM,
        (size_t)SDIM * TDIM, (size_t)CDIM * TDIM, (size_t)SDIM * CDIM);

    // 4) v_scores = scale * V X^T  [S,T]  (2-pass; must stay accurate pre-softmax)
    mma_gemm<2, false><<<dim3(TDIM / 128, SDIM / 128, NB), 256, SMEM>>>(
        Vh, Vl, Xh, nullptr, vsc, scale, CDIM, TDIM,
        (size_t)SDIM * CDIM, (size_t)TDIM * CDIM, (size_t)SDIM * TDIM);

    // P3 (row softmax over 4096, hi only)
    softrow4096_k<<<NB * SDIM, 512>>>(vsc, P3h);

    // 5) v_t = v + P3 X   (1-pass; residual-dominated, K=4096)
    mma_gemm<1, true><<<dim3(CDIM / 128, SDIM / 128, NB), 256, SMEM>>>(
        P3h, nullptr, XTh, vin, vtv, 1.0f, TDIM, CDIM,
        (size_t)SDIM * TDIM, (size_t)CDIM * TDIM, (size_t)SDIM * CDIM);
}

// round 11
// speedup vs baseline: 1.5818x; 1.0493x over previous
#include <cuda_runtime.h>
#include <cuda_fp16.h>
#include <cstdint>

#define NB 8
#define TDIM 4096
#define SDIM 512
#define CDIM 1024
#define NCHUNK 16
#define CHROWS (TDIM / NCHUNK)
#define NEG_INF (-3.0e38f)

typedef __half hf;

// ---------------- scratch (static device globals; no allocation) ----------------
__device__ float g_sc [(size_t)NB * TDIM * SDIM];
__device__ float g_vsc[(size_t)NB * SDIM * TDIM];
__device__ __align__(16) hf g_Xh [(size_t)NB * TDIM * CDIM], g_Xl [(size_t)NB * TDIM * CDIM];
__device__ __align__(16) hf g_XTh[(size_t)NB * CDIM * TDIM];
__device__ __align__(16) hf g_Kh [(size_t)NB * SDIM * CDIM];
__device__ __align__(16) hf g_Vh [(size_t)NB * SDIM * CDIM], g_Vl [(size_t)NB * SDIM * CDIM];
__device__ __align__(16) hf g_VTh[(size_t)NB * CDIM * SDIM];
__device__ __align__(16) hf g_Ph [(size_t)NB * TDIM * SDIM];
__device__ __align__(16) hf g_P2h[(size_t)NB * SDIM * TDIM];
__device__ __align__(16) hf g_P3h[(size_t)NB * SDIM * TDIM];
__device__ float g_pcm[NB * NCHUNK * SDIM], g_pcs[NB * NCHUNK * SDIM];
__device__ float g_cm [NB * SDIM], g_cs [NB * SDIM];

// ---------------- PTX helpers ----------------
__device__ __forceinline__ void cp16(uint32_t dst, const void* src) {
    asm volatile("cp.async.cg.shared.global [%0], [%1], 16;" :: "r"(dst), "l"(src));
}
__device__ __forceinline__ void cp_commit() {
    asm volatile("cp.async.commit_group;" ::: "memory");
}
template <int N>
__device__ __forceinline__ void cp_wait() {
    asm volatile("cp.async.wait_group %0;" :: "n"(N) : "memory");
}
__device__ __forceinline__ void ldsm4(uint32_t* r, uint32_t addr) {
    asm volatile("ldmatrix.sync.aligned.m8n8.x4.shared.b16 {%0,%1,%2,%3}, [%4];"
                 : "=r"(r[0]), "=r"(r[1]), "=r"(r[2]), "=r"(r[3]) : "r"(addr));
}
__device__ __forceinline__ void mma16816(float* d, const uint32_t* a, const uint32_t* b) {
    asm volatile(
        "mma.sync.aligned.m16n8k16.row.col.f32.f16.f16.f32 "
        "{%0,%1,%2,%3}, {%4,%5,%6,%7}, {%8,%9}, {%0,%1,%2,%3};"
        : "+f"(d[0]), "+f"(d[1]), "+f"(d[2]), "+f"(d[3])
        : "r"(a[0]), "r"(a[1]), "r"(a[2]), "r"(a[3]), "r"(b[0]), "r"(b[1]));
}
__device__ __forceinline__ void split1(float f, hf& h, hf& l) {
    h = __float2half_rn(f);
    l = __float2half_rn(f - __half2float(h));
}

// ---------------------------------------------------------------------------
// fp16 emulated GEMM on HMMA. Tile 128x128, 256 thr, warp tile 64x32;
// 3-stage cp.async (32KB/stage), 2 CTAs/SM.
// PASSES=2: BK=32; D = Ah*Bh + Al*Bh (A rows hold hi|lo in one 128B row).
// PASSES=1: BK=64; D = Ah*Bh (full 128B rows of A-hi and B-hi; half the
//           syncthreads per K of the 2-pass layout).
// ---------------------------------------------------------------------------
#define STAGE 32768
#define BOFF  16384

template <int PASSES, bool ADD>
__global__ void __launch_bounds__(256, 2)
mma_gemm(const hf* __restrict__ Ah, const hf* __restrict__ Al,
         const hf* __restrict__ Bh,
         const float* __restrict__ Res, float* __restrict__ C,
         float scale, int K, int Nglob, size_t sA, size_t sB, size_t sC)
{
    constexpr int BKC = (PASSES == 1) ? 64 : 32;

    extern __shared__ char dsm[];
    const uint32_t sbase = (uint32_t)__cvta_generic_to_shared(dsm);
    const int tid = threadIdx.x, wid = tid >> 5, lane = tid & 31;
    const int b = blockIdx.z, m0 = blockIdx.y * 128, n0 = blockIdx.x * 128;
    const int wm = wid & 1, wn = wid >> 1;

    const hf* pAh = Ah + (size_t)b * sA;
    const hf* pAl = (PASSES == 2) ? (Al + (size_t)b * sA) : nullptr;
    const hf* pBh = Bh + (size_t)b * sB;

    const int KT = K / BKC;

    auto load = [&](int kc, int s) {
        uint32_t st = sbase + s * STAGE;
#pragma unroll
        for (int t = 0; t < 8; t++) {
            int idx = t * 256 + tid;
            int reg = idx >> 10;               // 0 = A, 1 = B
            int ch  = idx & 1023;
            int row = ch >> 3, c = ch & 7;
            const hf* src;
            size_t goff;
            if (PASSES == 2) {
                int plane = c >> 2, cc = c & 3;    // hi chunks 0-3, lo chunks 4-7
                if (plane == 1 && reg == 1) continue;  // no B-lo
                src  = reg ? pBh : (plane ? pAl : pAh);
                goff = (size_t)((reg ? n0 : m0) + row) * K + kc * 32 + cc * 8;
            } else {
                src  = reg ? pBh : pAh;
                goff = (size_t)((reg ? n0 : m0) + row) * K + kc * 64 + c * 8;
            }
            uint32_t dst = st + (uint32_t)(reg * BOFF + row * 128 + ((c ^ (row & 7)) * 16));
            cp16(dst, (const char*)src + goff * 2);
        }
        cp_commit();
    };

    float acc[4][4][4];
#pragma unroll
    for (int mi = 0; mi < 4; mi++)
#pragma unroll
        for (int ni = 0; ni < 4; ni++)
#pragma unroll
            for (int j = 0; j < 4; j++) acc[mi][ni][j] = 0.f;

    const int rowa = wm * 64 + (lane & 15);
    const int ka   = lane >> 4;
    const int xa   = rowa & 7;
    const int rowb = wn * 32 + (lane & 7) + ((lane >> 4) << 3);
    const int kb   = (lane >> 3) & 1;
    const int xb   = rowb & 7;

    auto compute = [&](int s) {
        uint32_t st = sbase + s * STAGE;
        constexpr int NKS = (PASSES == 1) ? 4 : 2;  // k16 steps per chunk
#pragma unroll
        for (int ks = 0; ks < NKS; ks++) {
            uint32_t ah[4][4], al[4][4], bh[2][4];
#pragma unroll
            for (int mi = 0; mi < 4; mi++) {
                uint32_t rb = st + (uint32_t)((rowa + mi * 16) * 128);
                ldsm4(ah[mi], rb + (uint32_t)(((2 * ks + ka) ^ xa) * 16));
                if (PASSES == 2)
                    ldsm4(al[mi], rb + (uint32_t)(((4 + 2 * ks + ka) ^ xa) * 16));
            }
#pragma unroll
            for (int j = 0; j < 2; j++) {
                uint32_t rb = st + BOFF + (uint32_t)((rowb + j * 16) * 128);
                ldsm4(bh[j], rb + (uint32_t)(((2 * ks + kb) ^ xb) * 16));
            }
#pragma unroll
            for (int mi = 0; mi < 4; mi++)
#pragma unroll
                for (int j = 0; j < 2; j++) {
                    mma16816(acc[mi][2 * j],     ah[mi], bh[j]);
                    mma16816(acc[mi][2 * j + 1], ah[mi], bh[j] + 2);
                }
            if (PASSES == 2) {
#pragma unroll
                for (int mi = 0; mi < 4; mi++)
#pragma unroll
                    for (int j = 0; j < 2; j++) {
                        mma16816(acc[mi][2 * j],     al[mi], bh[j]);
                        mma16816(acc[mi][2 * j + 1], al[mi], bh[j] + 2);
                    }
            }
        }
    };

    load(0, 0);
    if (KT > 1) load(1, 1);

    for (int ci = 0; ci < KT; ci++) {
        if (ci < KT - 1) cp_wait<1>(); else cp_wait<0>();
        __syncthreads();
        if (ci + 2 < KT) load(ci + 2, (ci + 2) % 3);
        compute(ci % 3);
    }

    float* Co = C + (size_t)b * sC;
    const float* Rp = ADD ? (Res + (size_t)b * sC) : nullptr;
    const int rbase = m0 + wm * 64 + (lane >> 2);
    const int cbase = n0 + wn * 32 + (lane & 3) * 2;
#pragma unroll
    for (int mi = 0; mi < 4; mi++) {
#pragma unroll
        for (int ni = 0; ni < 4; ni++) {
#pragma unroll
            for (int h = 0; h < 2; h++) {
                int r = rbase + mi * 16 + h * 8;
                int c = cbase + ni * 8;
                float2 v;
                v.x = acc[mi][ni][2 * h]     * scale;
                v.y = acc[mi][ni][2 * h + 1] * scale;
                size_t go = (size_t)r * Nglob + c;
                if (ADD) {
                    float2 d = *(const float2*)(Rp + go);
                    v.x += d.x; v.y += d.y;
                }
                *(float2*)(Co + go) = v;
            }
        }
    }
}

// ---------------- fused conversion kernels ----------------
// split (hi+lo) + transposed split (hi only) in one pass
__global__ void stx_k(const float* __restrict__ in, hf* __restrict__ oh,
                      hf* __restrict__ ol, hf* __restrict__ ohT, int R, int Cc)
{
    __shared__ float t[32][33];
    int b = blockIdx.z;
    int c0 = blockIdx.x * 32, r0 = blockIdx.y * 32;
    const float* ip = in + (size_t)b * R * Cc;
    size_t nb = (size_t)b * R * Cc;
    int tx = threadIdx.x, ty = threadIdx.y;
#pragma unroll
    for (int i = 0; i < 4; i++) {
        int r = r0 + ty + i * 8;
        float v = ip[(size_t)r * Cc + c0 + tx];
        t[ty + i * 8][tx] = v;
        hf h, l;
        split1(v, h, l);
        oh[nb + (size_t)r * Cc + c0 + tx] = h;
        if (ol) ol[nb + (size_t)r * Cc + c0 + tx] = l;
    }
    __syncthreads();
#pragma unroll
    for (int i = 0; i < 4; i++) {
        int c = c0 + ty + i * 8;
        ohT[nb + (size_t)c * R + r0 + tx] = __float2half_rn(t[tx][ty + i * 8]);
    }
}

// hi-only conversion (K)
__global__ void splith_k(const float* __restrict__ in, hf* __restrict__ h, size_t n4)
{
    size_t i = (size_t)blockIdx.x * blockDim.x + threadIdx.x;
    if (i >= n4) return;
    float4 v = ((const float4*)in)[i];
    __half2* hp = (__half2*)h;
    hp[i * 2]     = __halves2half2(__float2half_rn(v.x), __float2half_rn(v.y));
    hp[i * 2 + 1] = __halves2half2(__float2half_rn(v.z), __float2half_rn(v.w));
}

// row softmax over 512 -> fp16 hi only
__global__ void softrow512_k(const float* __restrict__ S, hf* __restrict__ oh)
{
    int warp = threadIdx.x >> 5, lane = threadIdx.x & 31;
    size_t row = (size_t)blockIdx.x * 8 + warp;
    const float4* p4 = (const float4*)(S + row * SDIM);
    float4 v[4];
    float m = NEG_INF;
#pragma unroll
    for (int i = 0; i < 4; i++) {
        v[i] = p4[lane + i * 32];
        m = fmaxf(m, fmaxf(fmaxf(v[i].x, v[i].y), fmaxf(v[i].z, v[i].w)));
    }
#pragma unroll
    for (int o = 16; o > 0; o >>= 1) m = fmaxf(m, __shfl_xor_sync(0xffffffffu, m, o));
    float s = 0.f;
#pragma unroll
    for (int i = 0; i < 4; i++)
        s += __expf(v[i].x - m) + __expf(v[i].y - m) + __expf(v[i].z - m) + __expf(v[i].w - m);
#pragma unroll
    for (int o = 16; o > 0; o >>= 1) s += __shfl_xor_sync(0xffffffffu, s, o);
    float inv = __fdividef(1.0f, s);
    __half2* hp = (__half2*)(oh + row * SDIM);
#pragma unroll
    for (int i = 0; i < 4; i++) {
        int p = (lane + i * 32) * 2;
        hp[p]     = __halves2half2(__float2half_rn(__expf(v[i].x - m) * inv),
                                   __float2half_rn(__expf(v[i].y - m) * inv));
        hp[p + 1] = __halves2half2(__float2half_rn(__expf(v[i].z - m) * inv),
                                   __float2half_rn(__expf(v[i].w - m) * inv));
    }
}

// row softmax over 4096 -> fp16 hi only
__global__ void softrow4096_k(const float* __restrict__ S, hf* __restrict__ oh)
{
    __shared__ float sh[16];
    int tid = threadIdx.x, lane = tid & 31, warp = tid >> 5;
    size_t row = blockIdx.x;
    const float4* p4 = (const float4*)(S + row * TDIM);
    float4 v[2];
    float m = NEG_INF;
#pragma unroll
    for (int i = 0; i < 2; i++) {
        v[i] = p4[tid + i * 512];
        m = fmaxf(m, fmaxf(fmaxf(v[i].x, v[i].y), fmaxf(v[i].z, v[i].w)));
    }
#pragma unroll
    for (int o = 16; o > 0; o >>= 1) m = fmaxf(m, __shfl_xor_sync(0xffffffffu, m, o));
    if (!lane) sh[warp] = m;
    __syncthreads();
    if (tid < 16) {
        float t = sh[tid];
#pragma unroll
        for (int o = 8; o > 0; o >>= 1) t = fmaxf(t, __shfl_xor_sync(0xffffu, t, o));
        if (!tid) sh[0] = t;
    }
    __syncthreads();
    m = sh[0];
    __syncthreads();
    float s = 0.f;
#pragma unroll
    for (int i = 0; i < 2; i++)
        s += __expf(v[i].x - m) + __expf(v[i].y - m) + __expf(v[i].z - m) + __expf(v[i].w - m);
#pragma unroll
    for (int o = 16; o > 0; o >>= 1) s += __shfl_xor_sync(0xffffffffu, s, o);
    if (!lane) sh[warp] = s;
    __syncthreads();
    if (tid < 16) {
        float t = sh[tid];
#pragma unroll
        for (int o = 8; o > 0; o >>= 1) t += __shfl_xor_sync(0xffffu, t, o);
        if (!tid) sh[0] = t;
    }
    __syncthreads();
    float inv = __fdividef(1.0f, sh[0]);
    __half2* hp = (__half2*)(oh + row * TDIM);
#pragma unroll
    for (int i = 0; i < 2; i++) {
        int p = (tid + i * 512) * 2;
        hp[p]     = __halves2half2(__float2half_rn(__expf(v[i].x - m) * inv),
                                   __float2half_rn(__expf(v[i].y - m) * inv));
        hp[p + 1] = __halves2half2(__float2half_rn(__expf(v[i].z - m) * inv),
                                   __float2half_rn(__expf(v[i].w - m) * inv));
    }
}

// ---------------- column softmax (over T) pipeline ----------------
__global__ void colpart_k(const float* __restrict__ S, float* __restrict__ pm,
                          float* __restrict__ ps)
{
    int b = blockIdx.y, ch = blockIdx.x, s = threadIdx.x;
    const float* p = S + (size_t)b * TDIM * SDIM + (size_t)ch * CHROWS * SDIM + s;
    float m = NEG_INF, sum = 0.f;
    for (int t = 0; t < CHROWS; t++) {
        float v = p[(size_t)t * SDIM];
        float nm = fmaxf(m, v);
        sum = sum * __expf(m - nm) + __expf(v - nm);
        m = nm;
    }
    int o = (b * NCHUNK + ch) * SDIM + s;
    pm[o] = m; ps[o] = sum;
}

__global__ void colcomb_k(const float* __restrict__ pm, const float* __restrict__ ps,
                          float* __restrict__ cm, float* __restrict__ cs)
{
    int b = blockIdx.x, s = threadIdx.x;
    float m = NEG_INF;
#pragma unroll
    for (int c = 0; c < NCHUNK; c++) m = fmaxf(m, pm[(b * NCHUNK + c) * SDIM + s]);
    float sum = 0.f;
#pragma unroll
    for (int c = 0; c < NCHUNK; c++)
        sum += ps[(b * NCHUNK + c) * SDIM + s] * __expf(pm[(b * NCHUNK + c) * SDIM + s] - m);
    cm[b * SDIM + s] = m;
    cs[b * SDIM + s] = sum;
}

// col softmax + transpose -> [S,T] fp16 hi only
__global__ void pcolT_k(const float* __restrict__ sc, const float* __restrict__ cm,
                        const float* __restrict__ cs, hf* __restrict__ oh)
{
    __shared__ float t[32][33];
    int b = blockIdx.z;
    int s0 = blockIdx.x * 32, t0 = blockIdx.y * 32;
    const float* ip = sc + (size_t)b * TDIM * SDIM;
    int tx = threadIdx.x, ty = threadIdx.y;
#pragma unroll
    for (int i = 0; i < 4; i++)
        t[ty + i * 8][tx] = ip[(size_t)(t0 + ty + i * 8) * SDIM + s0 + tx];
    __syncthreads();
    size_t ob = (size_t)b * SDIM * TDIM;
#pragma unroll
    for (int i = 0; i < 4; i++) {
        int s = s0 + ty + i * 8;
        float m = cm[b * SDIM + s], inv = __fdividef(1.0f, cs[b * SDIM + s]);
        oh[ob + (size_t)s * TDIM + t0 + tx] =
            __float2half_rn(__expf(t[tx][ty + i * 8] - m) * inv);
    }
}

// ---------------- launch ----------------
extern "C" void kernel_launch(void* const* d_in, const int* in_sizes, int n_in,
                              void* d_out, int out_size)
{
    const float* x   = (const float*)d_in[0];
    const float* kin = (const float*)d_in[1];
    const float* vin = (const float*)d_in[2];

    float* att = (float*)d_out;
    float* ktv = att + (size_t)NB * TDIM * CDIM;
    float* vtv = ktv + (size_t)NB * SDIM * CDIM;

    float *sc, *vsc, *pcm, *pcs, *cm, *cs;
    hf *Xh, *Xl, *XTh, *Kh, *Vh, *Vl, *VTh;
    hf *Ph, *P2h, *P3h;
    cudaGetSymbolAddress((void**)&sc, g_sc);     cudaGetSymbolAddress((void**)&vsc, g_vsc);
    cudaGetSymbolAddress((void**)&pcm, g_pcm);   cudaGetSymbolAddress((void**)&pcs, g_pcs);
    cudaGetSymbolAddress((void**)&cm, g_cm);     cudaGetSymbolAddress((void**)&cs, g_cs);
    cudaGetSymbolAddress((void**)&Xh, g_Xh);     cudaGetSymbolAddress((void**)&Xl, g_Xl);
    cudaGetSymbolAddress((void**)&XTh, g_XTh);
    cudaGetSymbolAddress((void**)&Kh, g_Kh);
    cudaGetSymbolAddress((void**)&Vh, g_Vh);     cudaGetSymbolAddress((void**)&Vl, g_Vl);
    cudaGetSymbolAddress((void**)&VTh, g_VTh);
    cudaGetSymbolAddress((void**)&Ph, g_Ph);
    cudaGetSymbolAddress((void**)&P2h, g_P2h);
    cudaGetSymbolAddress((void**)&P3h, g_P3h);

    const int SMEM = 3 * STAGE;  // 98304
    cudaFuncSetAttribute(mma_gemm<2, false>, cudaFuncAttributeMaxDynamicSharedMemorySize, SMEM);
    cudaFuncSetAttribute(mma_gemm<1, false>, cudaFuncAttributeMaxDynamicSharedMemorySize, SMEM);
    cudaFuncSetAttribute(mma_gemm<1, true>,  cudaFuncAttributeMaxDynamicSharedMemorySize, SMEM);

    const float scale = 0.03125f;  // 1/sqrt(1024)

    // operand prep
    stx_k<<<dim3(CDIM / 32, TDIM / 32, NB), dim3(32, 8)>>>(x, Xh, Xl, XTh, TDIM, CDIM);
    {
        size_t n4 = (size_t)NB * SDIM * CDIM / 4;
        splith_k<<<(unsigned)((n4 + 255) / 256), 256>>>(kin, Kh, n4);
    }
    stx_k<<<dim3(CDIM / 32, SDIM / 32, NB), dim3(32, 8)>>>(vin, Vh, Vl, VTh, SDIM, CDIM);

    // 1) scores = scale * X K^T  [T,S]  (2-pass, BK=32; must stay accurate pre-softmax)
    mma_gemm<2, false><<<dim3(SDIM / 128, TDIM / 128, NB), 256, SMEM>>>(
        Xh, Xl, Kh, nullptr, sc, scale, CDIM, SDIM,
        (size_t)TDIM * CDIM, (size_t)SDIM * CDIM, (size_t)TDIM * SDIM);

    // softmax conversions
    softrow512_k<<<NB * TDIM / 8, 256>>>(sc, Ph);
    colpart_k<<<dim3(NCHUNK, NB), 512>>>(sc, pcm, pcs);
    colcomb_k<<<NB, 512>>>(pcm, pcs, cm, cs);
    pcolT_k<<<dim3(SDIM / 32, TDIM / 32, NB), dim3(32, 8)>>>(sc, cm, cs, P2h);

    // 2) att = P V   (1-pass, BK=64; K=512)
    mma_gemm<1, false><<<dim3(CDIM / 128, TDIM / 128, NB), 256, SMEM>>>(
        Ph, nullptr, VTh, nullptr, att, 1.0f, SDIM, CDIM,
        (size_t)TDIM * SDIM, (size_t)CDIM * SDIM, (size_t)TDIM * CDIM);

    // 3) k_t = k + P2^T X   (1-pass, BK=64; residual-dominated, K=4096)
    mma_gemm<1, true><<<dim3(CDIM / 128, SDIM / 128, NB), 256, SMEM>>>(
        P2h, nullptr, XTh, kin, ktv, 1.0f, TDIM, CDIM,
        (size_t)SDIM * TDIM, (size_t)CDIM * TDIM, (size_t)SDIM * CDIM);

    // 4) v_scores = scale * V X^T  [S,T]  (2-pass, BK=32)
    mma_gemm<2, false><<<dim3(TDIM / 128, SDIM / 128, NB), 256, SMEM>>>(
        Vh, Vl, Xh, nullptr, vsc, scale, CDIM, TDIM,
        (size_t)SDIM * CDIM, (size_t)TDIM * CDIM, (size_t)SDIM * TDIM);

    // P3 (row softmax over 4096, hi only)
    softrow4096_k<<<NB * SDIM, 512>>>(vsc, P3h);

    // 5) v_t = v + P3 X   (1-pass, BK=64; residual-dominated, K=4096)
    mma_gemm<1, true><<<dim3(CDIM / 128, SDIM / 128, NB), 256, SMEM>>>(
        P3h, nullptr, XTh, vin, vtv, 1.0f, TDIM, CDIM,
        (size_t)SDIM * TDIM, (size_t)CDIM * TDIM, (size_t)SDIM * CDIM);
}

// round 13
// speedup vs baseline: 1.6153x; 1.0212x over previous
#include <cuda_runtime.h>
#include <cuda_fp16.h>
#include <cstdint>

#define NB 8
#define TDIM 4096
#define SDIM 512
#define CDIM 1024
#define NCHUNK 16
#define CHROWS (TDIM / NCHUNK)
#define NEG_INF (-3.0e38f)

typedef __half hf;

// ---------------- scratch (static device globals; no allocation) ----------------
__device__ float g_sc [(size_t)NB * TDIM * SDIM];
__device__ float g_vsc[(size_t)NB * SDIM * TDIM];
__device__ __align__(16) hf g_Xh [(size_t)NB * TDIM * CDIM], g_Xl [(size_t)NB * TDIM * CDIM];
__device__ __align__(16) hf g_XTh[(size_t)NB * CDIM * TDIM];
__device__ __align__(16) hf g_Kh [(size_t)NB * SDIM * CDIM];
__device__ __align__(16) hf g_Vh [(size_t)NB * SDIM * CDIM], g_Vl [(size_t)NB * SDIM * CDIM];
__device__ __align__(16) hf g_VTh[(size_t)NB * CDIM * SDIM];
__device__ __align__(16) hf g_Ph [(size_t)NB * TDIM * SDIM];
__device__ __align__(16) hf g_P2h[(size_t)NB * SDIM * TDIM];
__device__ __align__(16) hf g_P3h[(size_t)NB * SDIM * TDIM];
__device__ float g_pcm[NB * NCHUNK * SDIM], g_pcs[NB * NCHUNK * SDIM];
__device__ float g_cm [NB * SDIM], g_cs [NB * SDIM];

// ---------------- PTX helpers ----------------
__device__ __forceinline__ void cp16(uint32_t dst, const void* src) {
    asm volatile("cp.async.cg.shared.global [%0], [%1], 16;" :: "r"(dst), "l"(src));
}
__device__ __forceinline__ void cp_commit() {
    asm volatile("cp.async.commit_group;" ::: "memory");
}
template <int N>
__device__ __forceinline__ void cp_wait() {
    asm volatile("cp.async.wait_group %0;" :: "n"(N) : "memory");
}
__device__ __forceinline__ void ldsm4(uint32_t* r, uint32_t addr) {
    asm volatile("ldmatrix.sync.aligned.m8n8.x4.shared.b16 {%0,%1,%2,%3}, [%4];"
                 : "=r"(r[0]), "=r"(r[1]), "=r"(r[2]), "=r"(r[3]) : "r"(addr));
}
__device__ __forceinline__ void mma16816(float* d, const uint32_t* a, const uint32_t* b) {
    asm volatile(
        "mma.sync.aligned.m16n8k16.row.col.f32.f16.f16.f32 "
        "{%0,%1,%2,%3}, {%4,%5,%6,%7}, {%8,%9}, {%0,%1,%2,%3};"
        : "+f"(d[0]), "+f"(d[1]), "+f"(d[2]), "+f"(d[3])
        : "r"(a[0]), "r"(a[1]), "r"(a[2]), "r"(a[3]), "r"(b[0]), "r"(b[1]));
}
__device__ __forceinline__ void split1(float f, hf& h, hf& l) {
    h = __float2half_rn(f);
    l = __float2half_rn(f - __half2float(h));
}

// ---------------------------------------------------------------------------
// fp16 emulated GEMM on HMMA. Tile 128x128, BK=64, 256 thr, warp tile 64x32.
// PASSES=2: stage = {Ah,Al,Bh} 3x16KB = 48KB, 2 stages (96KB), D = Ah*Bh+Al*Bh.
// PASSES=1: stage = {Ah,Bh}    2x16KB = 32KB, 3 stages (96KB), D = Ah*Bh.
// 2 CTAs/SM either way; one __syncthreads per 64-wide K chunk.
// ---------------------------------------------------------------------------
template <int PASSES, bool ADD>
__global__ void __launch_bounds__(256, 2)
mma_gemm(const hf* __restrict__ Ah, const hf* __restrict__ Al,
         const hf* __restrict__ Bh,
         const float* __restrict__ Res, float* __restrict__ C,
         float scale, int K, int Nglob, size_t sA, size_t sB, size_t sC)
{
    constexpr int NST  = (PASSES == 1) ? 3 : 2;         // pipeline stages
    constexpr int STG  = (PASSES == 1) ? 32768 : 49152; // bytes per stage
    constexpr int BOFC = (PASSES == 1) ? 16384 : 32768; // B tile offset in stage
    constexpr int NCH  = (PASSES == 1) ? 8 : 12;        // 16B chunks per thread

    extern __shared__ char dsm[];
    const uint32_t sbase = (uint32_t)__cvta_generic_to_shared(dsm);
    const int tid = threadIdx.x, wid = tid >> 5, lane = tid & 31;
    const int b = blockIdx.z, m0 = blockIdx.y * 128, n0 = blockIdx.x * 128;
    const int wm = wid & 1, wn = wid >> 1;

    const hf* pAh = Ah + (size_t)b * sA;
    const hf* pAl = (PASSES == 2) ? (Al + (size_t)b * sA) : nullptr;
    const hf* pBh = Bh + (size_t)b * sB;

    const int KT = K >> 6;     // 64-wide chunks

    auto load = [&](int kc, int s) {
        uint32_t st = sbase + s * STG;
#pragma unroll
        for (int t = 0; t < NCH; t++) {
            int idx = t * 256 + tid;
            int tile = idx >> 10;             // 0=Ah, 1=Al(2p)/Bh(1p), 2=Bh(2p)
            int ch = idx & 1023;
            int row = ch >> 3, c = ch & 7;
            const hf* src;
            int rbase;
            if (PASSES == 2) {
                src = (tile == 0) ? pAh : (tile == 1 ? pAl : pBh);
                rbase = (tile < 2) ? m0 : n0;
            } else {
                src = (tile == 0) ? pAh : pBh;
                rbase = (tile == 0) ? m0 : n0;
            }
            size_t goff = (size_t)(rbase + row) * K + kc * 64 + c * 8;
            uint32_t dst = st + (uint32_t)(tile * 16384 + row * 128 + ((c ^ (row & 7)) * 16));
            cp16(dst, (const char*)src + goff * 2);
        }
        cp_commit();
    };

    float acc[4][4][4];
#pragma unroll
    for (int mi = 0; mi < 4; mi++)
#pragma unroll
        for (int ni = 0; ni < 4; ni++)
#pragma unroll
            for (int j = 0; j < 4; j++) acc[mi][ni][j] = 0.f;

    const int rowa = wm * 64 + (lane & 15);
    const int ka   = lane >> 4;
    const int xa   = rowa & 7;
    const int rowb = wn * 32 + (lane & 7) + ((lane >> 4) << 3);
    const int kb   = (lane >> 3) & 1;
    const int xb   = rowb & 7;

    auto compute = [&](int s) {
        uint32_t st = sbase + s * STG;
#pragma unroll
        for (int ks = 0; ks < 4; ks++) {        // 4 k16 steps per 64-chunk
            uint32_t ah[4][4], al[4][4], bh[2][4];
#pragma unroll
            for (int mi = 0; mi < 4; mi++) {
                uint32_t rb = st + (uint32_t)((rowa + mi * 16) * 128);
                uint32_t co = (uint32_t)(((2 * ks + ka) ^ xa) * 16);
                ldsm4(ah[mi], rb + co);
                if (PASSES == 2)
                    ldsm4(al[mi], rb + 16384 + co);
            }
#pragma unroll
            for (int j = 0; j < 2; j++) {
                uint32_t rb = st + BOFC + (uint32_t)((rowb + j * 16) * 128);
                ldsm4(bh[j], rb + (uint32_t)(((2 * ks + kb) ^ xb) * 16));
            }
#pragma unroll
            for (int mi = 0; mi < 4; mi++)
#pragma unroll
                for (int j = 0; j < 2; j++) {
                    mma16816(acc[mi][2 * j],     ah[mi], bh[j]);
                    mma16816(acc[mi][2 * j + 1], ah[mi], bh[j] + 2);
                }
            if (PASSES == 2) {
#pragma unroll
                for (int mi = 0; mi < 4; mi++)
#pragma unroll
                    for (int j = 0; j < 2; j++) {
                        mma16816(acc[mi][2 * j],     al[mi], bh[j]);
                        mma16816(acc[mi][2 * j + 1], al[mi], bh[j] + 2);
                    }
            }
        }
    };

#pragma unroll
    for (int i = 0; i < NST - 1; i++)
        if (i < KT) load(i, i);

    for (int ci = 0; ci < KT; ci++) {
        if (ci < KT - (NST - 1)) cp_wait<NST - 2>(); else cp_wait<0>();
        __syncthreads();
        if (ci + NST - 1 < KT) load(ci + NST - 1, (ci + NST - 1) % NST);
        compute(ci % NST);
    }

    float* Co = C + (size_t)b * sC;
    const float* Rp = ADD ? (Res + (size_t)b * sC) : nullptr;
    const int rbase = m0 + wm * 64 + (lane >> 2);
    const int cbase = n0 + wn * 32 + (lane & 3) * 2;
#pragma unroll
    for (int mi = 0; mi < 4; mi++) {
#pragma unroll
        for (int ni = 0; ni < 4; ni++) {
#pragma unroll
            for (int h = 0; h < 2; h++) {
                int r = rbase + mi * 16 + h * 8;
                int c = cbase + ni * 8;
                float2 v;
                v.x = acc[mi][ni][2 * h]     * scale;
                v.y = acc[mi][ni][2 * h + 1] * scale;
                size_t go = (size_t)r * Nglob + c;
                if (ADD) {
                    float2 d = *(const float2*)(Rp + go);
                    v.x += d.x; v.y += d.y;
                }
                *(float2*)(Co + go) = v;
            }
        }
    }
}

// ---------------- fused conversion kernels ----------------
// split (hi+lo) + transposed split (hi only) in one pass
__global__ void stx_k(const float* __restrict__ in, hf* __restrict__ oh,
                      hf* __restrict__ ol, hf* __restrict__ ohT, int R, int Cc)
{
    __shared__ float t[32][33];
    int b = blockIdx.z;
    int c0 = blockIdx.x * 32, r0 = blockIdx.y * 32;
    const float* ip = in + (size_t)b * R * Cc;
    size_t nb = (size_t)b * R * Cc;
    int tx = threadIdx.x, ty = threadIdx.y;
#pragma unroll
    for (int i = 0; i < 4; i++) {
        int r = r0 + ty + i * 8;
        float v = ip[(size_t)r * Cc + c0 + tx];
        t[ty + i * 8][tx] = v;
        hf h, l;
        split1(v, h, l);
        oh[nb + (size_t)r * Cc + c0 + tx] = h;
        if (ol) ol[nb + (size_t)r * Cc + c0 + tx] = l;
    }
    __syncthreads();
#pragma unroll
    for (int i = 0; i < 4; i++) {
        int c = c0 + ty + i * 8;
        ohT[nb + (size_t)c * R + r0 + tx] = __float2half_rn(t[tx][ty + i * 8]);
    }
}

// hi-only conversion (K)
__global__ void splith_k(const float* __restrict__ in, hf* __restrict__ h, size_t n4)
{
    size_t i = (size_t)blockIdx.x * blockDim.x + threadIdx.x;
    if (i >= n4) return;
    float4 v = ((const float4*)in)[i];
    __half2* hp = (__half2*)h;
    hp[i * 2]     = __halves2half2(__float2half_rn(v.x), __float2half_rn(v.y));
    hp[i * 2 + 1] = __halves2half2(__float2half_rn(v.z), __float2half_rn(v.w));
}

// row softmax over 512 -> fp16 hi only
__global__ void softrow512_k(const float* __restrict__ S, hf* __restrict__ oh)
{
    int warp = threadIdx.x >> 5, lane = threadIdx.x & 31;
    size_t row = (size_t)blockIdx.x * 8 + warp;
    const float4* p4 = (const float4*)(S + row * SDIM);
    float4 v[4];
    float m = NEG_INF;
#pragma unroll
    for (int i = 0; i < 4; i++) {
        v[i] = p4[lane + i * 32];
        m = fmaxf(m, fmaxf(fmaxf(v[i].x, v[i].y), fmaxf(v[i].z, v[i].w)));
    }
#pragma unroll
    for (int o = 16; o > 0; o >>= 1) m = fmaxf(m, __shfl_xor_sync(0xffffffffu, m, o));
    float s = 0.f;
#pragma unroll
    for (int i = 0; i < 4; i++)
        s += __expf(v[i].x - m) + __expf(v[i].y - m) + __expf(v[i].z - m) + __expf(v[i].w - m);
#pragma unroll
    for (int o = 16; o > 0; o >>= 1) s += __shfl_xor_sync(0xffffffffu, s, o);
    float inv = __fdividef(1.0f, s);
    __half2* hp = (__half2*)(oh + row * SDIM);
#pragma unroll
    for (int i = 0; i < 4; i++) {
        int p = (lane + i * 32) * 2;
        hp[p]     = __halves2half2(__float2half_rn(__expf(v[i].x - m) * inv),
                                   __float2half_rn(__expf(v[i].y - m) * inv));
        hp[p + 1] = __halves2half2(__float2half_rn(__expf(v[i].z - m) * inv),
                                   __float2half_rn(__expf(v[i].w - m) * inv));
    }
}

// row softmax over 4096 -> fp16 hi only
__global__ void softrow4096_k(const float* __restrict__ S, hf* __restrict__ oh)
{
    __shared__ float sh[16];
    int tid = threadIdx.x, lane = tid & 31, warp = tid >> 5;
    size_t row = blockIdx.x;
    const float4* p4 = (const float4*)(S + row * TDIM);
    float4 v[2];
    float m = NEG_INF;
#pragma unroll
    for (int i = 0; i < 2; i++) {
        v[i] = p4[tid + i * 512];
        m = fmaxf(m, fmaxf(fmaxf(v[i].x, v[i].y), fmaxf(v[i].z, v[i].w)));
    }
#pragma unroll
    for (int o = 16; o > 0; o >>= 1) m = fmaxf(m, __shfl_xor_sync(0xffffffffu, m, o));
    if (!lane) sh[warp] = m;
    __syncthreads();
    if (tid < 16) {
        float t = sh[tid];
#pragma unroll
        for (int o = 8; o > 0; o >>= 1) t = fmaxf(t, __shfl_xor_sync(0xffffu, t, o));
        if (!tid) sh[0] = t;
    }
    __syncthreads();
    m = sh[0];
    __syncthreads();
    float s = 0.f;
#pragma unroll
    for (int i = 0; i < 2; i++)
        s += __expf(v[i].x - m) + __expf(v[i].y - m) + __expf(v[i].z - m) + __expf(v[i].w - m);
#pragma unroll
    for (int o = 16; o > 0; o >>= 1) s += __shfl_xor_sync(0xffffffffu, s, o);
    if (!lane) sh[warp] = s;
    __syncthreads();
    if (tid < 16) {
        float t = sh[tid];
#pragma unroll
        for (int o = 8; o > 0; o >>= 1) t += __shfl_xor_sync(0xffffu, t, o);
        if (!tid) sh[0] = t;
    }
    __syncthreads();
    float inv = __fdividef(1.0f, sh[0]);
    __half2* hp = (__half2*)(oh + row * TDIM);
#pragma unroll
    for (int i = 0; i < 2; i++) {
        int p = (tid + i * 512) * 2;
        hp[p]     = __halves2half2(__float2half_rn(__expf(v[i].x - m) * inv),
                                   __float2half_rn(__expf(v[i].y - m) * inv));
        hp[p + 1] = __halves2half2(__float2half_rn(__expf(v[i].z - m) * inv),
                                   __float2half_rn(__expf(v[i].w - m) * inv));
    }
}

// ---------------- column softmax (over T) pipeline ----------------
__global__ void colpart_k(const float* __restrict__ S, float* __restrict__ pm,
                          float* __restrict__ ps)
{
    int b = blockIdx.y, ch = blockIdx.x, s = threadIdx.x;
    const float* p = S + (size_t)b * TDIM * SDIM + (size_t)ch * CHROWS * SDIM + s;
    float m = NEG_INF, sum = 0.f;
    for (int t = 0; t < CHROWS; t++) {
        float v = p[(size_t)t * SDIM];
        float nm = fmaxf(m, v);
        sum = sum * __expf(m - nm) + __expf(v - nm);
        m = nm;
    }
    int o = (b * NCHUNK + ch) * SDIM + s;
    pm[o] = m; ps[o] = sum;
}

__global__ void colcomb_k(const float* __restrict__ pm, const float* __restrict__ ps,
                          float* __restrict__ cm, float* __restrict__ cs)
{
    int b = blockIdx.x, s = threadIdx.x;
    float m = NEG_INF;
#pragma unroll
    for (int c = 0; c < NCHUNK; c++) m = fmaxf(m, pm[(b * NCHUNK + c) * SDIM + s]);
    float sum = 0.f;
#pragma unroll
    for (int c = 0; c < NCHUNK; c++)
        sum += ps[(b * NCHUNK + c) * SDIM + s] * __expf(pm[(b * NCHUNK + c) * SDIM + s] - m);
    cm[b * SDIM + s] = m;
    cs[b * SDIM + s] = sum;
}

// col softmax + transpose -> [S,T] fp16 hi only
__global__ void pcolT_k(const float* __restrict__ sc, const float* __restrict__ cm,
                        const float* __restrict__ cs, hf* __restrict__ oh)
{
    __shared__ float t[32][33];
    int b = blockIdx.z;
    int s0 = blockIdx.x * 32, t0 = blockIdx.y * 32;
    const float* ip = sc + (size_t)b * TDIM * SDIM;
    int tx = threadIdx.x, ty = threadIdx.y;
#pragma unroll
    for (int i = 0; i < 4; i++)
        t[ty + i * 8][tx] = ip[(size_t)(t0 + ty + i * 8) * SDIM + s0 + tx];
    __syncthreads();
    size_t ob = (size_t)b * SDIM * TDIM;
#pragma unroll
    for (int i = 0; i < 4; i++) {
        int s = s0 + ty + i * 8;
        float m = cm[b * SDIM + s], inv = __fdividef(1.0f, cs[b * SDIM + s]);
        oh[ob + (size_t)s * TDIM + t0 + tx] =
            __float2half_rn(__expf(t[tx][ty + i * 8] - m) * inv);
    }
}

// ---------------- launch ----------------
extern "C" void kernel_launch(void* const* d_in, const int* in_sizes, int n_in,
                              void* d_out, int out_size)
{
    const float* x   = (const float*)d_in[0];
    const float* kin = (const float*)d_in[1];
    const float* vin = (const float*)d_in[2];

    float* att = (float*)d_out;
    float* ktv = att + (size_t)NB * TDIM * CDIM;
    float* vtv = ktv + (size_t)NB * SDIM * CDIM;

    float *sc, *vsc, *pcm, *pcs, *cm, *cs;
    hf *Xh, *Xl, *XTh, *Kh, *Vh, *Vl, *VTh;
    hf *Ph, *P2h, *P3h;
    cudaGetSymbolAddress((void**)&sc, g_sc);     cudaGetSymbolAddress((void**)&vsc, g_vsc);
    cudaGetSymbolAddress((void**)&pcm, g_pcm);   cudaGetSymbolAddress((void**)&pcs, g_pcs);
    cudaGetSymbolAddress((void**)&cm, g_cm);     cudaGetSymbolAddress((void**)&cs, g_cs);
    cudaGetSymbolAddress((void**)&Xh, g_Xh);     cudaGetSymbolAddress((void**)&Xl, g_Xl);
    cudaGetSymbolAddress((void**)&XTh, g_XTh);
    cudaGetSymbolAddress((void**)&Kh, g_Kh);
    cudaGetSymbolAddress((void**)&Vh, g_Vh);     cudaGetSymbolAddress((void**)&Vl, g_Vl);
    cudaGetSymbolAddress((void**)&VTh, g_VTh);
    cudaGetSymbolAddress((void**)&Ph, g_Ph);
    cudaGetSymbolAddress((void**)&P2h, g_P2h);
    cudaGetSymbolAddress((void**)&P3h, g_P3h);

    const int SMEM = 98304;  // 2x49152 (2-pass) == 3x32768 (1-pass)
    cudaFuncSetAttribute(mma_gemm<2, false>, cudaFuncAttributeMaxDynamicSharedMemorySize, SMEM);
    cudaFuncSetAttribute(mma_gemm<1, false>, cudaFuncAttributeMaxDynamicSharedMemorySize, SMEM);
    cudaFuncSetAttribute(mma_gemm<1, true>,  cudaFuncAttributeMaxDynamicSharedMemorySize, SMEM);

    const float scale = 0.03125f;  // 1/sqrt(1024)

    // operand prep
    stx_k<<<dim3(CDIM / 32, TDIM / 32, NB), dim3(32, 8)>>>(x, Xh, Xl, XTh, TDIM, CDIM);
    {
        size_t n4 = (size_t)NB * SDIM * CDIM / 4;
        splith_k<<<(unsigned)((n4 + 255) / 256), 256>>>(kin, Kh, n4);
    }
    stx_k<<<dim3(CDIM / 32, SDIM / 32, NB), dim3(32, 8)>>>(vin, Vh, Vl, VTh, SDIM, CDIM);

    // 1) scores = scale * X K^T  [T,S]  (2-pass, BK=64)
    mma_gemm<2, false><<<dim3(SDIM / 128, TDIM / 128, NB), 256, SMEM>>>(
        Xh, Xl, Kh, nullptr, sc, scale, CDIM, SDIM,
        (size_t)TDIM * CDIM, (size_t)SDIM * CDIM, (size_t)TDIM * SDIM);

    // softmax conversions
    softrow512_k<<<NB * TDIM / 8, 256>>>(sc, Ph);
    colpart_k<<<dim3(NCHUNK, NB), 512>>>(sc, pcm, pcs);
    colcomb_k<<<NB, 512>>>(pcm, pcs, cm, cs);
    pcolT_k<<<dim3(SDIM / 32, TDIM / 32, NB), dim3(32, 8)>>>(sc, cm, cs, P2h);

    // 2) att = P V   (1-pass, BK=64; K=512)
    mma_gemm<1, false><<<dim3(CDIM / 128, TDIM / 128, NB), 256, SMEM>>>(
        Ph, nullptr, VTh, nullptr, att, 1.0f, SDIM, CDIM,
        (size_t)TDIM * SDIM, (size_t)CDIM * SDIM, (size_t)TDIM * CDIM);

    // 3) k_t = k + P2^T X   (1-pass, BK=64; residual-dominated, K=4096)
    mma_gemm<1, true><<<dim3(CDIM / 128, SDIM / 128, NB), 256, SMEM>>>(
        P2h, nullptr, XTh, kin, ktv, 1.0f, TDIM, CDIM,
        (size_t)SDIM * TDIM, (size_t)CDIM * TDIM, (size_t)SDIM * CDIM);

    // 4) v_scores = scale * V X^T  [S,T]  (2-pass, BK=64)
    mma_gemm<2, false><<<dim3(TDIM / 128, SDIM / 128, NB), 256, SMEM>>>(
        Vh, Vl, Xh, nullptr, vsc, scale, CDIM, TDIM,
        (size_t)SDIM * CDIM, (size_t)TDIM * CDIM, (size_t)SDIM * TDIM);

    // P3 (row softmax over 4096, hi only)
    softrow4096_k<<<NB * SDIM, 512>>>(vsc, P3h);

    // 5) v_t = v + P3 X   (1-pass, BK=64; residual-dominated, K=4096)
    mma_gemm<1, true><<<dim3(CDIM / 128, SDIM / 128, NB), 256, SMEM>>>(
        P3h, nullptr, XTh, vin, vtv, 1.0f, TDIM, CDIM,
        (size_t)SDIM * TDIM, (size_t)CDIM * TDIM, (size_t)SDIM * CDIM);
}

// round 14
// speedup vs baseline: 1.6542x; 1.0241x over previous
#include <cuda_runtime.h>
#include <cuda_fp16.h>
#include <cstdint>

#define NB 8
#define TDIM 4096
#define SDIM 512
#define CDIM 1024
#define NCHUNK 16
#define NRCH 512                    /* 8-row chunks per batch for column partials */
#define NEG_INF (-3.0e38f)

typedef __half hf;

// ---------------- scratch (static device globals; no allocation) ----------------
__device__ float g_sc [(size_t)NB * TDIM * SDIM];
__device__ float g_vsc[(size_t)NB * SDIM * TDIM];
__device__ __align__(16) hf g_Xh [(size_t)NB * TDIM * CDIM], g_Xl [(size_t)NB * TDIM * CDIM];
__device__ __align__(16) hf g_XTh[(size_t)NB * CDIM * TDIM];
__device__ __align__(16) hf g_Kh [(size_t)NB * SDIM * CDIM];
__device__ __align__(16) hf g_Vh [(size_t)NB * SDIM * CDIM], g_Vl [(size_t)NB * SDIM * CDIM];
__device__ __align__(16) hf g_VTh[(size_t)NB * CDIM * SDIM];
__device__ __align__(16) hf g_Ph [(size_t)NB * TDIM * SDIM];
__device__ __align__(16) hf g_P2h[(size_t)NB * SDIM * TDIM];
__device__ __align__(16) hf g_P3h[(size_t)NB * SDIM * TDIM];
__device__ float g_pmL[(size_t)NB * NRCH * SDIM], g_psL[(size_t)NB * NRCH * SDIM];
__device__ float g_pcm[NB * NCHUNK * SDIM], g_pcs[NB * NCHUNK * SDIM];
__device__ float g_cm [NB * SDIM], g_cs [NB * SDIM];
__device__ float g_rm [NB * TDIM], g_rs [NB * TDIM];

// ---------------- PTX helpers ----------------
__device__ __forceinline__ void cp16(uint32_t dst, const void* src) {
    asm volatile("cp.async.cg.shared.global [%0], [%1], 16;" :: "r"(dst), "l"(src));
}
__device__ __forceinline__ void cp_commit() {
    asm volatile("cp.async.commit_group;" ::: "memory");
}
template <int N>
__device__ __forceinline__ void cp_wait() {
    asm volatile("cp.async.wait_group %0;" :: "n"(N) : "memory");
}
__device__ __forceinline__ void ldsm4(uint32_t* r, uint32_t addr) {
    asm volatile("ldmatrix.sync.aligned.m8n8.x4.shared.b16 {%0,%1,%2,%3}, [%4];"
                 : "=r"(r[0]), "=r"(r[1]), "=r"(r[2]), "=r"(r[3]) : "r"(addr));
}
__device__ __forceinline__ void mma16816(float* d, const uint32_t* a, const uint32_t* b) {
    asm volatile(
        "mma.sync.aligned.m16n8k16.row.col.f32.f16.f16.f32 "
        "{%0,%1,%2,%3}, {%4,%5,%6,%7}, {%8,%9}, {%0,%1,%2,%3};"
        : "+f"(d[0]), "+f"(d[1]), "+f"(d[2]), "+f"(d[3])
        : "r"(a[0]), "r"(a[1]), "r"(a[2]), "r"(a[3]), "r"(b[0]), "r"(b[1]));
}
__device__ __forceinline__ void split1(float f, hf& h, hf& l) {
    h = __float2half_rn(f);
    l = __float2half_rn(f - __half2float(h));
}

// ---------------------------------------------------------------------------
// fp16 emulated GEMM on HMMA. Tile 128x128, BK=64, 256 thr, warp tile 64x32.
// PASSES=2: stage = {Ah,Al,Bh} 3x16KB = 48KB, 2 stages; D = Ah*Bh + Al*Bh.
// PASSES=1: stage = {Ah,Bh}    2x16KB = 32KB, 3 stages; D = Ah*Bh.
// ---------------------------------------------------------------------------
template <int PASSES, bool ADD>
__global__ void __launch_bounds__(256, 2)
mma_gemm(const hf* __restrict__ Ah, const hf* __restrict__ Al,
         const hf* __restrict__ Bh,
         const float* __restrict__ Res, float* __restrict__ C,
         float scale, int K, int Nglob, size_t sA, size_t sB, size_t sC)
{
    constexpr int NST  = (PASSES == 1) ? 3 : 2;
    constexpr int STG  = (PASSES == 1) ? 32768 : 49152;
    constexpr int BOFC = (PASSES == 1) ? 16384 : 32768;
    constexpr int NCH  = (PASSES == 1) ? 8 : 12;

    extern __shared__ char dsm[];
    const uint32_t sbase = (uint32_t)__cvta_generic_to_shared(dsm);
    const int tid = threadIdx.x, wid = tid >> 5, lane = tid & 31;
    const int b = blockIdx.z, m0 = blockIdx.y * 128, n0 = blockIdx.x * 128;
    const int wm = wid & 1, wn = wid >> 1;

    const hf* pAh = Ah + (size_t)b * sA;
    const hf* pAl = (PASSES == 2) ? (Al + (size_t)b * sA) : nullptr;
    const hf* pBh = Bh + (size_t)b * sB;

    const int KT = K >> 6;

    auto load = [&](int kc, int s) {
        uint32_t st = sbase + s * STG;
#pragma unroll
        for (int t = 0; t < NCH; t++) {
            int idx = t * 256 + tid;
            int tile = idx >> 10;
            int ch = idx & 1023;
            int row = ch >> 3, c = ch & 7;
            const hf* src;
            int rbase;
            if (PASSES == 2) {
                src = (tile == 0) ? pAh : (tile == 1 ? pAl : pBh);
                rbase = (tile < 2) ? m0 : n0;
            } else {
                src = (tile == 0) ? pAh : pBh;
                rbase = (tile == 0) ? m0 : n0;
            }
            size_t goff = (size_t)(rbase + row) * K + kc * 64 + c * 8;
            uint32_t dst = st + (uint32_t)(tile * 16384 + row * 128 + ((c ^ (row & 7)) * 16));
            cp16(dst, (const char*)src + goff * 2);
        }
        cp_commit();
    };

    float acc[4][4][4];
#pragma unroll
    for (int mi = 0; mi < 4; mi++)
#pragma unroll
        for (int ni = 0; ni < 4; ni++)
#pragma unroll
            for (int j = 0; j < 4; j++) acc[mi][ni][j] = 0.f;

    const int rowa = wm * 64 + (lane & 15);
    const int ka   = lane >> 4;
    const int xa   = rowa & 7;
    const int rowb = wn * 32 + (lane & 7) + ((lane >> 4) << 3);
    const int kb   = (lane >> 3) & 1;
    const int xb   = rowb & 7;

    auto compute = [&](int s) {
        uint32_t st = sbase + s * STG;
#pragma unroll
        for (int ks = 0; ks < 4; ks++) {
            uint32_t ah[4][4], al[4][4], bh[2][4];
#pragma unroll
            for (int mi = 0; mi < 4; mi++) {
                uint32_t rb = st + (uint32_t)((rowa + mi * 16) * 128);
                uint32_t co = (uint32_t)(((2 * ks + ka) ^ xa) * 16);
                ldsm4(ah[mi], rb + co);
                if (PASSES == 2)
                    ldsm4(al[mi], rb + 16384 + co);
            }
#pragma unroll
            for (int j = 0; j < 2; j++) {
                uint32_t rb = st + BOFC + (uint32_t)((rowb + j * 16) * 128);
                ldsm4(bh[j], rb + (uint32_t)(((2 * ks + kb) ^ xb) * 16));
            }
#pragma unroll
            for (int mi = 0; mi < 4; mi++)
#pragma unroll
                for (int j = 0; j < 2; j++) {
                    mma16816(acc[mi][2 * j],     ah[mi], bh[j]);
                    mma16816(acc[mi][2 * j + 1], ah[mi], bh[j] + 2);
                }
            if (PASSES == 2) {
#pragma unroll
                for (int mi = 0; mi < 4; mi++)
#pragma unroll
                    for (int j = 0; j < 2; j++) {
                        mma16816(acc[mi][2 * j],     al[mi], bh[j]);
                        mma16816(acc[mi][2 * j + 1], al[mi], bh[j] + 2);
                    }
            }
        }
    };

#pragma unroll
    for (int i = 0; i < NST - 1; i++)
        if (i < KT) load(i, i);

    for (int ci = 0; ci < KT; ci++) {
        if (ci < KT - (NST - 1)) cp_wait<NST - 2>(); else cp_wait<0>();
        __syncthreads();
        if (ci + NST - 1 < KT) load(ci + NST - 1, (ci + NST - 1) % NST);
        compute(ci % NST);
    }

    float* Co = C + (size_t)b * sC;
    const float* Rp = ADD ? (Res + (size_t)b * sC) : nullptr;
    const int rbase = m0 + wm * 64 + (lane >> 2);
    const int cbase = n0 + wn * 32 + (lane & 3) * 2;
#pragma unroll
    for (int mi = 0; mi < 4; mi++) {
#pragma unroll
        for (int ni = 0; ni < 4; ni++) {
#pragma unroll
            for (int h = 0; h < 2; h++) {
                int r = rbase + mi * 16 + h * 8;
                int c = cbase + ni * 8;
                float2 v;
                v.x = acc[mi][ni][2 * h]     * scale;
                v.y = acc[mi][ni][2 * h + 1] * scale;
                size_t go = (size_t)r * Nglob + c;
                if (ADD) {
                    float2 d = *(const float2*)(Rp + go);
                    v.x += d.x; v.y += d.y;
                }
                *(float2*)(Co + go) = v;
            }
        }
    }
}

// ---------------- conversion kernels ----------------
__global__ void stx_k(const float* __restrict__ in, hf* __restrict__ oh,
                      hf* __restrict__ ol, hf* __restrict__ ohT, int R, int Cc)
{
    __shared__ float t[32][33];
    int b = blockIdx.z;
    int c0 = blockIdx.x * 32, r0 = blockIdx.y * 32;
    const float* ip = in + (size_t)b * R * Cc;
    size_t nb = (size_t)b * R * Cc;
    int tx = threadIdx.x, ty = threadIdx.y;
#pragma unroll
    for (int i = 0; i < 4; i++) {
        int r = r0 + ty + i * 8;
        float v = ip[(size_t)r * Cc + c0 + tx];
        t[ty + i * 8][tx] = v;
        hf h, l;
        split1(v, h, l);
        oh[nb + (size_t)r * Cc + c0 + tx] = h;
        if (ol) ol[nb + (size_t)r * Cc + c0 + tx] = l;
    }
    __syncthreads();
#pragma unroll
    for (int i = 0; i < 4; i++) {
        int c = c0 + ty + i * 8;
        ohT[nb + (size_t)c * R + r0 + tx] = __float2half_rn(t[tx][ty + i * 8]);
    }
}

__global__ void splith_k(const float* __restrict__ in, hf* __restrict__ h, size_t n4)
{
    size_t i = (size_t)blockIdx.x * blockDim.x + threadIdx.x;
    if (i >= n4) return;
    float4 v = ((const float4*)in)[i];
    __half2* hp = (__half2*)h;
    hp[i * 2]     = __halves2half2(__float2half_rn(v.x), __float2half_rn(v.y));
    hp[i * 2 + 1] = __halves2half2(__float2half_rn(v.z), __float2half_rn(v.w));
}

// ---------------------------------------------------------------------------
// FUSED: row softmax over 512 (-> Ph, rm, rs) + per-8-row column partials
// (-> pmL/psL). One read of sc. Block = 256 thr (8 warps), 8 rows.
// ---------------------------------------------------------------------------
__global__ void softfuse512_k(const float* __restrict__ S, hf* __restrict__ oh,
                              float* __restrict__ rmg, float* __restrict__ rsg,
                              float* __restrict__ pm, float* __restrict__ ps)
{
    __shared__ float sv[SDIM * 9];           // [s][warp], stride 9 (18 KB)
    int warp = threadIdx.x >> 5, lane = threadIdx.x & 31;
    int b = blockIdx.y, rb = blockIdx.x;
    size_t row = (size_t)b * TDIM + rb * 8 + warp;
    const float4* p4 = (const float4*)(S + row * SDIM);
    float4 v[4];
    float m = NEG_INF;
#pragma unroll
    for (int i = 0; i < 4; i++) {
        v[i] = p4[lane + i * 32];
        m = fmaxf(m, fmaxf(fmaxf(v[i].x, v[i].y), fmaxf(v[i].z, v[i].w)));
        int c0 = 4 * (lane + i * 32);
        sv[(c0 + 0) * 9 + warp] = v[i].x;
        sv[(c0 + 1) * 9 + warp] = v[i].y;
        sv[(c0 + 2) * 9 + warp] = v[i].z;
        sv[(c0 + 3) * 9 + warp] = v[i].w;
    }
#pragma unroll
    for (int o = 16; o > 0; o >>= 1) m = fmaxf(m, __shfl_xor_sync(0xffffffffu, m, o));
    float s = 0.f;
#pragma unroll
    for (int i = 0; i < 4; i++)
        s += __expf(v[i].x - m) + __expf(v[i].y - m) + __expf(v[i].z - m) + __expf(v[i].w - m);
#pragma unroll
    for (int o = 16; o > 0; o >>= 1) s += __shfl_xor_sync(0xffffffffu, s, o);
    if (!lane) { rmg[row] = m; rsg[row] = s; }
    float inv = __fdividef(1.0f, s);
    __half2* hp = (__half2*)(oh + row * SDIM);
#pragma unroll
    for (int i = 0; i < 4; i++) {
        int p = (lane + i * 32) * 2;
        hp[p]     = __halves2half2(__float2half_rn(__expf(v[i].x - m) * inv),
                                   __float2half_rn(__expf(v[i].y - m) * inv));
        hp[p + 1] = __halves2half2(__float2half_rn(__expf(v[i].z - m) * inv),
                                   __float2half_rn(__expf(v[i].w - m) * inv));
    }
    __syncthreads();
    // phase 2: column partials over the 8 rows; each thread 2 columns
#pragma unroll
    for (int h = 0; h < 2; h++) {
        int sc_ = threadIdx.x + h * 256;
        float cmx = NEG_INF;
#pragma unroll
        for (int w = 0; w < 8; w++) cmx = fmaxf(cmx, sv[sc_ * 9 + w]);
        float csum = 0.f;
#pragma unroll
        for (int w = 0; w < 8; w++) csum += __expf(sv[sc_ * 9 + w] - cmx);
        size_t o = ((size_t)b * NRCH + rb) * SDIM + sc_;
        pm[o] = cmx; ps[o] = csum;
    }
}

// combine 512 row-chunks -> 16
__global__ void colcomb1_k(const float* __restrict__ pm, const float* __restrict__ ps,
                           float* __restrict__ pm2, float* __restrict__ ps2)
{
    int b = blockIdx.y, g = blockIdx.x, s = threadIdx.x;
    float m = NEG_INF, sum = 0.f;
    for (int c = 0; c < NRCH / NCHUNK; c++) {
        size_t idx = ((size_t)b * NRCH + g * (NRCH / NCHUNK) + c) * SDIM + s;
        float mm = pm[idx];
        float nm = fmaxf(m, mm);
        sum = sum * __expf(m - nm) + ps[idx] * __expf(mm - nm);
        m = nm;
    }
    pm2[(b * NCHUNK + g) * SDIM + s] = m;
    ps2[(b * NCHUNK + g) * SDIM + s] = sum;
}

// combine 16 -> final cm/cs
__global__ void colcomb_k(const float* __restrict__ pm, const float* __restrict__ ps,
                          float* __restrict__ cm, float* __restrict__ cs)
{
    int b = blockIdx.x, s = threadIdx.x;
    float m = NEG_INF;
#pragma unroll
    for (int c = 0; c < NCHUNK; c++) m = fmaxf(m, pm[(b * NCHUNK + c) * SDIM + s]);
    float sum = 0.f;
#pragma unroll
    for (int c = 0; c < NCHUNK; c++)
        sum += ps[(b * NCHUNK + c) * SDIM + s] * __expf(pm[(b * NCHUNK + c) * SDIM + s] - m);
    cm[b * SDIM + s] = m;
    cs[b * SDIM + s] = sum;
}

// col softmax + transpose from Ph (not sc): P2[s,t] = Ph[t,s]*rs[t]*exp(rm[t]-cm[s])/cs[s]
__global__ void pcolT_k(const hf* __restrict__ Ph, const float* __restrict__ rmg,
                        const float* __restrict__ rsg, const float* __restrict__ cm,
                        const float* __restrict__ cs, hf* __restrict__ oh)
{
    __shared__ float t[32][33];
    int b = blockIdx.z;
    int s0 = blockIdx.x * 32, t0 = blockIdx.y * 32;
    const hf* ip = Ph + (size_t)b * TDIM * SDIM;
    int tx = threadIdx.x, ty = threadIdx.y;
#pragma unroll
    for (int i = 0; i < 4; i++) {
        int tr = t0 + ty + i * 8;
        t[ty + i * 8][tx] = __half2float(ip[(size_t)tr * SDIM + s0 + tx]);
    }
    __syncthreads();
    size_t ob = (size_t)b * SDIM * TDIM;
#pragma unroll
    for (int i = 0; i < 4; i++) {
        int s = s0 + ty + i * 8;
        int tcol = t0 + tx;
        float cminv = __fdividef(1.0f, cs[b * SDIM + s]);
        float cmv = cm[b * SDIM + s];
        float f = rsg[b * TDIM + tcol] * __expf(rmg[b * TDIM + tcol] - cmv) * cminv;
        oh[ob + (size_t)s * TDIM + t0 + tx] = __float2half_rn(t[tx][ty + i * 8] * f);
    }
}

// row softmax over 4096 -> fp16 hi only
__global__ void softrow4096_k(const float* __restrict__ S, hf* __restrict__ oh)
{
    __shared__ float sh[16];
    int tid = threadIdx.x, lane = tid & 31, warp = tid >> 5;
    size_t row = blockIdx.x;
    const float4* p4 = (const float4*)(S + row * TDIM);
    float4 v[2];
    float m = NEG_INF;
#pragma unroll
    for (int i = 0; i < 2; i++) {
        v[i] = p4[tid + i * 512];
        m = fmaxf(m, fmaxf(fmaxf(v[i].x, v[i].y), fmaxf(v[i].z, v[i].w)));
    }
#pragma unroll
    for (int o = 16; o > 0; o >>= 1) m = fmaxf(m, __shfl_xor_sync(0xffffffffu, m, o));
    if (!lane) sh[warp] = m;
    __syncthreads();
    if (tid < 16) {
        float t = sh[tid];
#pragma unroll
        for (int o = 8; o > 0; o >>= 1) t = fmaxf(t, __shfl_xor_sync(0xffffu, t, o));
        if (!tid) sh[0] = t;
    }
    __syncthreads();
    m = sh[0];
    __syncthreads();
    float s = 0.f;
#pragma unroll
    for (int i = 0; i < 2; i++)
        s += __expf(v[i].x - m) + __expf(v[i].y - m) + __expf(v[i].z - m) + __expf(v[i].w - m);
#pragma unroll
    for (int o = 16; o > 0; o >>= 1) s += __shfl_xor_sync(0xffffffffu, s, o);
    if (!lane) sh[warp] = s;
    __syncthreads();
    if (tid < 16) {
        float t = sh[tid];
#pragma unroll
        for (int o = 8; o > 0; o >>= 1) t += __shfl_xor_sync(0xffffu, t, o);
        if (!tid) sh[0] = t;
    }
    __syncthreads();
    float inv = __fdividef(1.0f, sh[0]);
    __half2* hp = (__half2*)(oh + row * TDIM);
#pragma unroll
    for (int i = 0; i < 2; i++) {
        int p = (tid + i * 512) * 2;
        hp[p]     = __halves2half2(__float2half_rn(__expf(v[i].x - m) * inv),
                                   __float2half_rn(__expf(v[i].y - m) * inv));
        hp[p + 1] = __halves2half2(__float2half_rn(__expf(v[i].z - m) * inv),
                                   __float2half_rn(__expf(v[i].w - m) * inv));
    }
}

// ---------------- launch ----------------
extern "C" void kernel_launch(void* const* d_in, const int* in_sizes, int n_in,
                              void* d_out, int out_size)
{
    const float* x   = (const float*)d_in[0];
    const float* kin = (const float*)d_in[1];
    const float* vin = (const float*)d_in[2];

    float* att = (float*)d_out;
    float* ktv = att + (size_t)NB * TDIM * CDIM;
    float* vtv = ktv + (size_t)NB * SDIM * CDIM;

    float *sc, *vsc, *pmL, *psL, *pcm, *pcs, *cm, *cs, *rm, *rs;
    hf *Xh, *Xl, *XTh, *Kh, *Vh, *Vl, *VTh;
    hf *Ph, *P2h, *P3h;
    cudaGetSymbolAddress((void**)&sc, g_sc);     cudaGetSymbolAddress((void**)&vsc, g_vsc);
    cudaGetSymbolAddress((void**)&pmL, g_pmL);   cudaGetSymbolAddress((void**)&psL, g_psL);
    cudaGetSymbolAddress((void**)&pcm, g_pcm);   cudaGetSymbolAddress((void**)&pcs, g_pcs);
    cudaGetSymbolAddress((void**)&cm, g_cm);     cudaGetSymbolAddress((void**)&cs, g_cs);
    cudaGetSymbolAddress((void**)&rm, g_rm);     cudaGetSymbolAddress((void**)&rs, g_rs);
    cudaGetSymbolAddress((void**)&Xh, g_Xh);     cudaGetSymbolAddress((void**)&Xl, g_Xl);
    cudaGetSymbolAddress((void**)&XTh, g_XTh);
    cudaGetSymbolAddress((void**)&Kh, g_Kh);
    cudaGetSymbolAddress((void**)&Vh, g_Vh);     cudaGetSymbolAddress((void**)&Vl, g_Vl);
    cudaGetSymbolAddress((void**)&VTh, g_VTh);
    cudaGetSymbolAddress((void**)&Ph, g_Ph);
    cudaGetSymbolAddress((void**)&P2h, g_P2h);
    cudaGetSymbolAddress((void**)&P3h, g_P3h);

    const int SMEM = 98304;
    cudaFuncSetAttribute(mma_gemm<2, false>, cudaFuncAttributeMaxDynamicSharedMemorySize, SMEM);
    cudaFuncSetAttribute(mma_gemm<1, false>, cudaFuncAttributeMaxDynamicSharedMemorySize, SMEM);
    cudaFuncSetAttribute(mma_gemm<1, true>,  cudaFuncAttributeMaxDynamicSharedMemorySize, SMEM);

    const float scale = 0.03125f;  // 1/sqrt(1024)

    // operand prep
    stx_k<<<dim3(CDIM / 32, TDIM / 32, NB), dim3(32, 8)>>>(x, Xh, Xl, XTh, TDIM, CDIM);
    {
        size_t n4 = (size_t)NB * SDIM * CDIM / 4;
        splith_k<<<(unsigned)((n4 + 255) / 256), 256>>>(kin, Kh, n4);
    }
    stx_k<<<dim3(CDIM / 32, SDIM / 32, NB), dim3(32, 8)>>>(vin, Vh, Vl, VTh, SDIM, CDIM);

    // 1) scores = scale * X K^T  [T,S]  (2-pass, BK=64)
    mma_gemm<2, false><<<dim3(SDIM / 128, TDIM / 128, NB), 256, SMEM>>>(
        Xh, Xl, Kh, nullptr, sc, scale, CDIM, SDIM,
        (size_t)TDIM * CDIM, (size_t)SDIM * CDIM, (size_t)TDIM * SDIM);

    // fused row softmax + column partials (single sc read)
    softfuse512_k<<<dim3(NRCH, NB), 256>>>(sc, Ph, rm, rs, pmL, psL);
    colcomb1_k<<<dim3(NCHUNK, NB), SDIM>>>(pmL, psL, pcm, pcs);
    colcomb_k<<<NB, SDIM>>>(pcm, pcs, cm, cs);
    pcolT_k<<<dim3(SDIM / 32, TDIM / 32, NB), dim3(32, 8)>>>(Ph, rm, rs, cm, cs, P2h);

    // 2) att = P V   (1-pass, BK=64; K=512)
    mma_gemm<1, false><<<dim3(CDIM / 128, TDIM / 128, NB), 256, SMEM>>>(
        Ph, nullptr, VTh, nullptr, att, 1.0f, SDIM, CDIM,
        (size_t)TDIM * SDIM, (size_t)CDIM * SDIM, (size_t)TDIM * CDIM);

    // 3) k_t = k + P2^T X   (1-pass, BK=64; K=4096)
    mma_gemm<1, true><<<dim3(CDIM / 128, SDIM / 128, NB), 256, SMEM>>>(
        P2h, nullptr, XTh, kin, ktv, 1.0f, TDIM, CDIM,
        (size_t)SDIM * TDIM, (size_t)CDIM * TDIM, (size_t)SDIM * CDIM);

    // 4) v_scores = scale * V X^T  [S,T]  (2-pass, BK=64)
    mma_gemm<2, false><<<dim3(TDIM / 128, SDIM / 128, NB), 256, SMEM>>>(
        Vh, Vl, Xh, nullptr, vsc, scale, CDIM, TDIM,
        (size_t)SDIM * CDIM, (size_t)TDIM * CDIM, (size_t)SDIM * TDIM);

    // P3 (row softmax over 4096, hi only)
    softrow4096_k<<<NB * SDIM, 512>>>(vsc, P3h);

    // 5) v_t = v + P3 X   (1-pass, BK=64; K=4096)
    mma_gemm<1, true><<<dim3(CDIM / 128, SDIM / 128, NB), 256, SMEM>>>(
        P3h, nullptr, XTh, vin, vtv, 1.0f, TDIM, CDIM,
        (size_t)SDIM * TDIM, (size_t)CDIM * TDIM, (size_t)SDIM * CDIM);
}